// round 2
// baseline (speedup 1.0000x reference)
#include <cuda_runtime.h>
#include <cuda_bf16.h>
#include <float.h>

// Problem constants
#define BB   8
#define NN   8192
#define MM   4096
#define CC   128
#define KNN  16
#define CO   256          // output channels of both layers
#define CI1  131          // 3 + 128
#define ROWS (BB*MM*KNN)  // 524288
#define QTOT (BB*MM)      // 32768
#define NEWPOS_ELEMS (QTOT*3)   // 98304

// ---------------- static scratch (allocation-free rule) ----------------
__device__ float g_P [ (size_t)BB*NN*CO ];       // 64 MB   points @ W1p^T
__device__ float g_h1[ (size_t)ROWS*CO ];        // 512 MB  layer1 pre-activations
__device__ float g_h2[ (size_t)ROWS*CO ];        // 512 MB  layer2 pre-activations
__device__ int   g_knn[ ROWS ];                  // 2 MB
__device__ float g_sum1[CO], g_sumsq1[CO], g_sum2[CO], g_sumsq2[CO];
__device__ float g_sc1[CO], g_sh1[CO], g_sc2[CO], g_sh2[CO];

// ---------------- zero stats ----------------
__global__ void zero_stats_kernel() {
    int t = threadIdx.x;
    if (t < CO) { g_sum1[t]=0.f; g_sumsq1[t]=0.f; g_sum2[t]=0.f; g_sumsq2[t]=0.f; }
}

// ---------------- kNN (one thread per query, register top-16) ----------------
__global__ __launch_bounds__(128)
void knn_kernel(const float* __restrict__ pos, const int* __restrict__ idx,
                float* __restrict__ out_newpos)
{
    __shared__ float4 sp[2048];
    const int q = blockIdx.x * 128 + threadIdx.x;       // 0..32767
    const int b = q >> 12;                               // q / 4096
    const float* pb = pos + (size_t)b * NN * 3;

    const int nq = idx[q];
    const float qx = pb[nq*3+0], qy = pb[nq*3+1], qz = pb[nq*3+2];
    out_newpos[q*3+0] = qx; out_newpos[q*3+1] = qy; out_newpos[q*3+2] = qz;
    const float qn = qx*qx + qy*qy + qz*qz;

    float dist[KNN]; int ind[KNN];
#pragma unroll
    for (int j = 0; j < KNN; j++) { dist[j] = FLT_MAX; ind[j] = 0x7fffffff; }
    float wd = FLT_MAX; int wi = 0x7fffffff, wj = 0;

    for (int c0 = 0; c0 < NN; c0 += 2048) {
        __syncthreads();
        for (int i = threadIdx.x; i < 2048; i += 128) {
            float x = pb[(c0+i)*3+0], y = pb[(c0+i)*3+1], z = pb[(c0+i)*3+2];
            sp[i] = make_float4(x, y, z, x*x + y*y + z*z);
        }
        __syncthreads();
#pragma unroll 4
        for (int i = 0; i < 2048; i++) {
            float4 p = sp[i];
            float qp = qx*p.x + qy*p.y + qz*p.z;
            float d  = qn - 2.0f*qp + p.w;               // same expansion as reference
            if (d < wd) {
                int nidx = c0 + i;
#pragma unroll
                for (int j = 0; j < KNN; j++) if (j == wj) { dist[j] = d; ind[j] = nidx; }
                wd = dist[0]; wi = ind[0]; wj = 0;
#pragma unroll
                for (int j = 1; j < KNN; j++) {
                    if (dist[j] > wd || (dist[j] == wd && ind[j] > wi)) {
                        wd = dist[j]; wi = ind[j]; wj = j;
                    }
                }
            }
        }
    }
#pragma unroll
    for (int j = 0; j < KNN; j++) g_knn[q*KNN + j] = ind[j];
}

// ---------------- generic tiled SGEMM: C[M,256] = op(A)[M,K] * B^T  ----------------
// B element (o,c) at Bw[o*ldb + boff + c].  Optional: per-K-channel BN+ReLU on A load,
// bias add, and per-output-channel sum/sumsq stats.
template<bool BN_A, bool HAS_BIAS, bool STATS>
__global__ __launch_bounds__(256, 2)
void gemm_kernel(const float* __restrict__ A, int lda,
                 const float* __restrict__ Bw, int ldb, int boff,
                 float* __restrict__ C, int Kdim,
                 const float* __restrict__ scA, const float* __restrict__ shA,
                 const float* __restrict__ bias,
                 float* __restrict__ gsum, float* __restrict__ gsq)
{
    const int BM = 128, BN = 128, BK = 16;
    __shared__ float As[BK][BM];
    __shared__ float Bs[BK][BN];
    __shared__ float sSum[BN], sSq[BN];

    const int t  = threadIdx.x;
    const int tx = t & 15, ty = t >> 4;
    const int rowBase = blockIdx.x * BM;
    const int colBase = blockIdx.y * BN;

    if (STATS && t < BN) { sSum[t] = 0.f; sSq[t] = 0.f; }

    float acc[8][8];
#pragma unroll
    for (int i = 0; i < 8; i++)
#pragma unroll
        for (int j = 0; j < 8; j++) acc[i][j] = 0.f;

    for (int k0 = 0; k0 < Kdim; k0 += BK) {
        // A tile: 128x16, two float4 per thread, transpose into As[k][row]
#pragma unroll
        for (int l = 0; l < 2; l++) {
            int fid = t + l*256;
            int row = fid >> 2, c4 = (fid & 3) * 4;
            float4 v = *(const float4*)(A + (size_t)(rowBase + row)*lda + k0 + c4);
            if (BN_A) {
                int c = k0 + c4;
                v.x = fmaxf(0.f, fmaf(v.x, scA[c+0], shA[c+0]));
                v.y = fmaxf(0.f, fmaf(v.y, scA[c+1], shA[c+1]));
                v.z = fmaxf(0.f, fmaf(v.z, scA[c+2], shA[c+2]));
                v.w = fmaxf(0.f, fmaf(v.w, scA[c+3], shA[c+3]));
            }
            As[c4+0][row] = v.x; As[c4+1][row] = v.y;
            As[c4+2][row] = v.z; As[c4+3][row] = v.w;
        }
        // B tile: Bs[c][o]
#pragma unroll
        for (int l = 0; l < 8; l++) {
            int e = t + l*256;
            int c = e & 15, o = e >> 4;
            Bs[c][o] = Bw[(size_t)(colBase + o)*ldb + boff + k0 + c];
        }
        __syncthreads();
#pragma unroll
        for (int kk = 0; kk < BK; kk++) {
            float4 a0 = *(const float4*)&As[kk][ty*8];
            float4 a1 = *(const float4*)&As[kk][ty*8+4];
            float4 b0 = *(const float4*)&Bs[kk][tx*8];
            float4 b1 = *(const float4*)&Bs[kk][tx*8+4];
            float aR[8] = {a0.x,a0.y,a0.z,a0.w,a1.x,a1.y,a1.z,a1.w};
            float bR[8] = {b0.x,b0.y,b0.z,b0.w,b1.x,b1.y,b1.z,b1.w};
#pragma unroll
            for (int i = 0; i < 8; i++)
#pragma unroll
                for (int j = 0; j < 8; j++)
                    acc[i][j] = fmaf(aR[i], bR[j], acc[i][j]);
        }
        __syncthreads();
    }

    float csum[8], csq[8];
#pragma unroll
    for (int j = 0; j < 8; j++) { csum[j] = 0.f; csq[j] = 0.f; }

#pragma unroll
    for (int i = 0; i < 8; i++) {
        int row = rowBase + ty*8 + i;
        float vj[8];
#pragma unroll
        for (int j = 0; j < 8; j++) {
            float v = acc[i][j];
            if (HAS_BIAS) v += bias[colBase + tx*8 + j];
            vj[j] = v;
            if (STATS) { csum[j] += v; csq[j] += v*v; }
        }
        float* cp = C + (size_t)row*CO + colBase + tx*8;
        *(float4*)cp       = make_float4(vj[0], vj[1], vj[2], vj[3]);
        *(float4*)(cp + 4) = make_float4(vj[4], vj[5], vj[6], vj[7]);
    }
    if (STATS) {
#pragma unroll
        for (int j = 0; j < 8; j++) {
            atomicAdd(&sSum[tx*8+j], csum[j]);
            atomicAdd(&sSq [tx*8+j], csq[j]);
        }
        __syncthreads();
        if (t < BN) {
            atomicAdd(&gsum[colBase + t], sSum[t]);
            atomicAdd(&gsq [colBase + t], sSq[t]);
        }
    }
}

// ---------------- assemble h1 = P[knn] + W1r*rel + b1  (+ stats) ----------------
__global__ __launch_bounds__(256)
void assemble_h1_kernel(const float* __restrict__ pos, const int* __restrict__ idx,
                        const float* __restrict__ W1, const float* __restrict__ b1)
{
    const int RPB = 64;
    __shared__ int   s_pb[RPB];
    __shared__ float s_r[RPB][3];
    const int base = blockIdx.x * RPB;
    const int t = threadIdx.x;
    if (t < RPB) {
        int r  = base + t;
        int b  = r >> 16;                 // / (4096*16)
        int m  = (r >> 4) & 4095;
        int nn = g_knn[r];
        const float* pb = pos + (size_t)b * NN * 3;
        int nq = idx[b*MM + m];
        s_r[t][0] = pb[nn*3+0] - pb[nq*3+0];
        s_r[t][1] = pb[nn*3+1] - pb[nq*3+1];
        s_r[t][2] = pb[nn*3+2] - pb[nq*3+2];
        s_pb[t]   = (b*NN + nn) * CO;
    }
    __syncthreads();
    const int o = t;                      // 256 channels
    const float w0 = W1[o*CI1+0], w1 = W1[o*CI1+1], w2 = W1[o*CI1+2], bb = b1[o];
    float ls = 0.f, lss = 0.f;
#pragma unroll 4
    for (int rr = 0; rr < RPB; rr++) {
        float v = g_P[(size_t)s_pb[rr] + o];
        v = v + bb + w0*s_r[rr][0] + w1*s_r[rr][1] + w2*s_r[rr][2];
        g_h1[(size_t)(base + rr)*CO + o] = v;
        ls += v; lss += v*v;
    }
    atomicAdd(&g_sum1[o], ls);
    atomicAdd(&g_sumsq1[o], lss);
}

// ---------------- finalize BN: scale/shift from sum/sumsq ----------------
__global__ void finalize_bn_kernel(const float* __restrict__ sum, const float* __restrict__ sq,
                                   const float* __restrict__ g,   const float* __restrict__ beta,
                                   float* __restrict__ sc, float* __restrict__ sh)
{
    int o = threadIdx.x;
    const float inv = 1.0f / (float)ROWS;
    float mean = sum[o] * inv;
    float var  = sq[o] * inv - mean*mean;
    float rstd = rsqrtf(var + 1e-5f);
    float s = g[o] * rstd;
    sc[o] = s;
    sh[o] = fmaf(-mean, s, beta[o]);
}

// ---------------- max-pool over K with BN2+ReLU (monotone affine) ----------------
__global__ __launch_bounds__(256)
void maxpool_kernel(float* __restrict__ out)
{
    int t = blockIdx.x * 256 + threadIdx.x;   // 0 .. 32768*64
    int row = t >> 6, cg = t & 63;
    const float* bp = g_h2 + (size_t)row * (KNN*CO) + cg*4;
    float4 mx = *(const float4*)bp;
    float4 mn = mx;
#pragma unroll
    for (int k = 1; k < KNN; k++) {
        float4 v = *(const float4*)(bp + (size_t)k*CO);
        mx.x = fmaxf(mx.x, v.x); mx.y = fmaxf(mx.y, v.y);
        mx.z = fmaxf(mx.z, v.z); mx.w = fmaxf(mx.w, v.w);
        mn.x = fminf(mn.x, v.x); mn.y = fminf(mn.y, v.y);
        mn.z = fminf(mn.z, v.z); mn.w = fminf(mn.w, v.w);
    }
    int c = cg*4;
    float4 r;
    {
        float s0=g_sc2[c+0], s1=g_sc2[c+1], s2=g_sc2[c+2], s3=g_sc2[c+3];
        float h0=g_sh2[c+0], h1=g_sh2[c+1], h2=g_sh2[c+2], h3=g_sh2[c+3];
        r.x = fmaxf(0.f, fmaf(s0 >= 0.f ? mx.x : mn.x, s0, h0));
        r.y = fmaxf(0.f, fmaf(s1 >= 0.f ? mx.y : mn.y, s1, h1));
        r.z = fmaxf(0.f, fmaf(s2 >= 0.f ? mx.z : mn.z, s2, h2));
        r.w = fmaxf(0.f, fmaf(s3 >= 0.f ? mx.w : mn.w, s3, h3));
    }
    *(float4*)(out + NEWPOS_ELEMS + (size_t)row*CO + c) = r;
}

// ---------------- launch ----------------
extern "C" void kernel_launch(void* const* d_in, const int* in_sizes, int n_in,
                              void* d_out, int out_size)
{
    const float* pos    = (const float*)d_in[0];
    const float* points = (const float*)d_in[1];
    const int*   idx    = (const int*)  d_in[2];
    const float* W1     = (const float*)d_in[3];
    const float* b1     = (const float*)d_in[4];
    const float* g1     = (const float*)d_in[5];
    const float* beta1  = (const float*)d_in[6];
    const float* W2     = (const float*)d_in[7];
    const float* b2     = (const float*)d_in[8];
    const float* g2     = (const float*)d_in[9];
    const float* beta2  = (const float*)d_in[10];
    float* out = (float*)d_out;

    float *pP, *pH1, *pH2, *pSum1, *pSq1, *pSum2, *pSq2, *pSc1, *pSh1, *pSc2, *pSh2;
    cudaGetSymbolAddress((void**)&pP,   g_P);
    cudaGetSymbolAddress((void**)&pH1,  g_h1);
    cudaGetSymbolAddress((void**)&pH2,  g_h2);
    cudaGetSymbolAddress((void**)&pSum1,g_sum1);
    cudaGetSymbolAddress((void**)&pSq1, g_sumsq1);
    cudaGetSymbolAddress((void**)&pSum2,g_sum2);
    cudaGetSymbolAddress((void**)&pSq2, g_sumsq2);
    cudaGetSymbolAddress((void**)&pSc1, g_sc1);
    cudaGetSymbolAddress((void**)&pSh1, g_sh1);
    cudaGetSymbolAddress((void**)&pSc2, g_sc2);
    cudaGetSymbolAddress((void**)&pSh2, g_sh2);

    zero_stats_kernel<<<1, 256>>>();

    // kNN + new_pos output
    knn_kernel<<<QTOT/128, 128>>>(pos, idx, out);

    // P = points @ W1p^T   (A: [65536,128], B: W1 rows, cols 3..130)
    gemm_kernel<false, false, false><<<dim3((BB*NN)/128, CO/128), 256>>>(
        points, CC, W1, CI1, 3, pP, CC,
        nullptr, nullptr, nullptr, nullptr, nullptr);

    // h1 = P[knn] + W1r*rel + b1   (+ stats1)
    assemble_h1_kernel<<<ROWS/64, 256>>>(pos, idx, W1, b1);

    finalize_bn_kernel<<<1, 256>>>(pSum1, pSq1, g1, beta1, pSc1, pSh1);

    // h2 = relu(bn1(h1)) @ W2^T + b2   (+ stats2)
    gemm_kernel<true, true, true><<<dim3(ROWS/128, CO/128), 256>>>(
        pH1, CO, W2, CO, 0, pH2, CO,
        pSc1, pSh1, b2, pSum2, pSq2);

    finalize_bn_kernel<<<1, 256>>>(pSum2, pSq2, g2, beta2, pSc2, pSh2);

    // out new_points = relu(bn2(max/min_k h2))
    maxpool_kernel<<<(QTOT*64)/256, 256>>>(out);
}

// round 3
// speedup vs baseline: 1.0008x; 1.0008x over previous
#include <cuda_runtime.h>
#include <cuda_bf16.h>
#include <float.h>

// Problem constants
#define BB   8
#define NN   8192
#define MM   4096
#define CC   128
#define KNN  16
#define CO   256          // output channels of both layers
#define CI1  131          // 3 + 128
#define ROWS (BB*MM*KNN)  // 524288
#define QTOT (BB*MM)      // 32768
#define NEWPOS_ELEMS (QTOT*3)   // 98304

// ---------------- static scratch (allocation-free rule) ----------------
__device__ float g_P [ (size_t)BB*NN*CO ];       // 64 MB   points @ W1p^T
__device__ float g_h1[ (size_t)ROWS*CO ];        // 512 MB  layer1 pre-activations
__device__ float g_h2[ (size_t)ROWS*CO ];        // 512 MB  layer2 pre-activations
__device__ int   g_knn[ ROWS ];                  // 2 MB
__device__ float g_sum1[CO], g_sumsq1[CO], g_sum2[CO], g_sumsq2[CO];
__device__ float g_sc1[CO], g_sh1[CO], g_sc2[CO], g_sh2[CO];

// ---------------- zero stats ----------------
__global__ void zero_stats_kernel() {
    int t = threadIdx.x;
    if (t < CO) { g_sum1[t]=0.f; g_sumsq1[t]=0.f; g_sum2[t]=0.f; g_sumsq2[t]=0.f; }
}

// ---------------- kNN (one thread per query, register top-16) ----------------
__global__ __launch_bounds__(128)
void knn_kernel(const float* __restrict__ pos, const int* __restrict__ idx,
                float* __restrict__ out_newpos)
{
    __shared__ float4 sp[2048];
    const int q = blockIdx.x * 128 + threadIdx.x;       // 0..32767
    const int b = q >> 12;                               // q / 4096
    const float* pb = pos + (size_t)b * NN * 3;

    const int nq = idx[q];
    const float qx = pb[nq*3+0], qy = pb[nq*3+1], qz = pb[nq*3+2];
    out_newpos[q*3+0] = qx; out_newpos[q*3+1] = qy; out_newpos[q*3+2] = qz;
    const float qn = qx*qx + qy*qy + qz*qz;

    float dist[KNN]; int ind[KNN];
#pragma unroll
    for (int j = 0; j < KNN; j++) { dist[j] = FLT_MAX; ind[j] = 0x7fffffff; }
    float wd = FLT_MAX; int wi = 0x7fffffff, wj = 0;

    for (int c0 = 0; c0 < NN; c0 += 2048) {
        __syncthreads();
        for (int i = threadIdx.x; i < 2048; i += 128) {
            float x = pb[(c0+i)*3+0], y = pb[(c0+i)*3+1], z = pb[(c0+i)*3+2];
            sp[i] = make_float4(x, y, z, x*x + y*y + z*z);
        }
        __syncthreads();
#pragma unroll 4
        for (int i = 0; i < 2048; i++) {
            float4 p = sp[i];
            float qp = qx*p.x + qy*p.y + qz*p.z;
            float d  = qn - 2.0f*qp + p.w;               // same expansion as reference
            if (d < wd) {
                int nidx = c0 + i;
#pragma unroll
                for (int j = 0; j < KNN; j++) if (j == wj) { dist[j] = d; ind[j] = nidx; }
                wd = dist[0]; wi = ind[0]; wj = 0;
#pragma unroll
                for (int j = 1; j < KNN; j++) {
                    if (dist[j] > wd || (dist[j] == wd && ind[j] > wi)) {
                        wd = dist[j]; wi = ind[j]; wj = j;
                    }
                }
            }
        }
    }
#pragma unroll
    for (int j = 0; j < KNN; j++) g_knn[q*KNN + j] = ind[j];
}

// ---------------- generic tiled SGEMM: C[M,256] = op(A)[M,K] * B^T  ----------------
// B element (o,c) at Bw[o*ldb + boff + c].  Optional: per-K-channel BN+ReLU on A load,
// bias add, and per-output-channel sum/sumsq stats.
template<bool BN_A, bool HAS_BIAS, bool STATS>
__global__ __launch_bounds__(256, 2)
void gemm_kernel(const float* __restrict__ A, int lda,
                 const float* __restrict__ Bw, int ldb, int boff,
                 float* __restrict__ C, int Kdim,
                 const float* __restrict__ scA, const float* __restrict__ shA,
                 const float* __restrict__ bias,
                 float* __restrict__ gsum, float* __restrict__ gsq)
{
    const int BM = 128, BN = 128, BK = 16;
    __shared__ float As[BK][BM];
    __shared__ float Bs[BK][BN];
    __shared__ float sSum[BN], sSq[BN];

    const int t  = threadIdx.x;
    const int tx = t & 15, ty = t >> 4;
    const int rowBase = blockIdx.x * BM;
    const int colBase = blockIdx.y * BN;

    if (STATS && t < BN) { sSum[t] = 0.f; sSq[t] = 0.f; }

    float acc[8][8];
#pragma unroll
    for (int i = 0; i < 8; i++)
#pragma unroll
        for (int j = 0; j < 8; j++) acc[i][j] = 0.f;

    for (int k0 = 0; k0 < Kdim; k0 += BK) {
        // A tile: 128x16, two float4 per thread, transpose into As[k][row]
#pragma unroll
        for (int l = 0; l < 2; l++) {
            int fid = t + l*256;
            int row = fid >> 2, c4 = (fid & 3) * 4;
            float4 v = *(const float4*)(A + (size_t)(rowBase + row)*lda + k0 + c4);
            if (BN_A) {
                int c = k0 + c4;
                v.x = fmaxf(0.f, fmaf(v.x, scA[c+0], shA[c+0]));
                v.y = fmaxf(0.f, fmaf(v.y, scA[c+1], shA[c+1]));
                v.z = fmaxf(0.f, fmaf(v.z, scA[c+2], shA[c+2]));
                v.w = fmaxf(0.f, fmaf(v.w, scA[c+3], shA[c+3]));
            }
            As[c4+0][row] = v.x; As[c4+1][row] = v.y;
            As[c4+2][row] = v.z; As[c4+3][row] = v.w;
        }
        // B tile: Bs[c][o]
#pragma unroll
        for (int l = 0; l < 8; l++) {
            int e = t + l*256;
            int c = e & 15, o = e >> 4;
            Bs[c][o] = Bw[(size_t)(colBase + o)*ldb + boff + k0 + c];
        }
        __syncthreads();
#pragma unroll
        for (int kk = 0; kk < BK; kk++) {
            float4 a0 = *(const float4*)&As[kk][ty*8];
            float4 a1 = *(const float4*)&As[kk][ty*8+4];
            float4 b0 = *(const float4*)&Bs[kk][tx*8];
            float4 b1 = *(const float4*)&Bs[kk][tx*8+4];
            float aR[8] = {a0.x,a0.y,a0.z,a0.w,a1.x,a1.y,a1.z,a1.w};
            float bR[8] = {b0.x,b0.y,b0.z,b0.w,b1.x,b1.y,b1.z,b1.w};
#pragma unroll
            for (int i = 0; i < 8; i++)
#pragma unroll
                for (int j = 0; j < 8; j++)
                    acc[i][j] = fmaf(aR[i], bR[j], acc[i][j]);
        }
        __syncthreads();
    }

    float csum[8], csq[8];
#pragma unroll
    for (int j = 0; j < 8; j++) { csum[j] = 0.f; csq[j] = 0.f; }

#pragma unroll
    for (int i = 0; i < 8; i++) {
        int row = rowBase + ty*8 + i;
        float vj[8];
#pragma unroll
        for (int j = 0; j < 8; j++) {
            float v = acc[i][j];
            if (HAS_BIAS) v += bias[colBase + tx*8 + j];
            vj[j] = v;
            if (STATS) { csum[j] += v; csq[j] += v*v; }
        }
        float* cp = C + (size_t)row*CO + colBase + tx*8;
        *(float4*)cp       = make_float4(vj[0], vj[1], vj[2], vj[3]);
        *(float4*)(cp + 4) = make_float4(vj[4], vj[5], vj[6], vj[7]);
    }
    if (STATS) {
#pragma unroll
        for (int j = 0; j < 8; j++) {
            atomicAdd(&sSum[tx*8+j], csum[j]);
            atomicAdd(&sSq [tx*8+j], csq[j]);
        }
        __syncthreads();
        if (t < BN) {
            atomicAdd(&gsum[colBase + t], sSum[t]);
            atomicAdd(&gsq [colBase + t], sSq[t]);
        }
    }
}

// ---------------- assemble h1 = P[knn] + W1r*rel + b1  (+ stats) ----------------
__global__ __launch_bounds__(256)
void assemble_h1_kernel(const float* __restrict__ pos, const int* __restrict__ idx,
                        const float* __restrict__ W1, const float* __restrict__ b1)
{
    const int RPB = 64;
    __shared__ int   s_pb[RPB];
    __shared__ float s_r[RPB][3];
    const int base = blockIdx.x * RPB;
    const int t = threadIdx.x;
    if (t < RPB) {
        int r  = base + t;
        int b  = r >> 16;                 // / (4096*16)
        int m  = (r >> 4) & 4095;
        int nn = g_knn[r];
        const float* pb = pos + (size_t)b * NN * 3;
        int nq = idx[b*MM + m];
        s_r[t][0] = pb[nn*3+0] - pb[nq*3+0];
        s_r[t][1] = pb[nn*3+1] - pb[nq*3+1];
        s_r[t][2] = pb[nn*3+2] - pb[nq*3+2];
        s_pb[t]   = (b*NN + nn) * CO;
    }
    __syncthreads();
    const int o = t;                      // 256 channels
    const float w0 = W1[o*CI1+0], w1 = W1[o*CI1+1], w2 = W1[o*CI1+2], bb = b1[o];
    float ls = 0.f, lss = 0.f;
#pragma unroll 4
    for (int rr = 0; rr < RPB; rr++) {
        float v = g_P[(size_t)s_pb[rr] + o];
        v = v + bb + w0*s_r[rr][0] + w1*s_r[rr][1] + w2*s_r[rr][2];
        g_h1[(size_t)(base + rr)*CO + o] = v;
        ls += v; lss += v*v;
    }
    atomicAdd(&g_sum1[o], ls);
    atomicAdd(&g_sumsq1[o], lss);
}

// ---------------- finalize BN: scale/shift from sum/sumsq ----------------
__global__ void finalize_bn_kernel(const float* __restrict__ sum, const float* __restrict__ sq,
                                   const float* __restrict__ g,   const float* __restrict__ beta,
                                   float* __restrict__ sc, float* __restrict__ sh)
{
    int o = threadIdx.x;
    const float inv = 1.0f / (float)ROWS;
    float mean = sum[o] * inv;
    float var  = sq[o] * inv - mean*mean;
    float rstd = rsqrtf(var + 1e-5f);
    float s = g[o] * rstd;
    sc[o] = s;
    sh[o] = fmaf(-mean, s, beta[o]);
}

// ---------------- max-pool over K with BN2+ReLU (monotone affine) ----------------
__global__ __launch_bounds__(256)
void maxpool_kernel(float* __restrict__ out)
{
    int t = blockIdx.x * 256 + threadIdx.x;   // 0 .. 32768*64
    int row = t >> 6, cg = t & 63;
    const float* bp = g_h2 + (size_t)row * (KNN*CO) + cg*4;
    float4 mx = *(const float4*)bp;
    float4 mn = mx;
#pragma unroll
    for (int k = 1; k < KNN; k++) {
        float4 v = *(const float4*)(bp + (size_t)k*CO);
        mx.x = fmaxf(mx.x, v.x); mx.y = fmaxf(mx.y, v.y);
        mx.z = fmaxf(mx.z, v.z); mx.w = fmaxf(mx.w, v.w);
        mn.x = fminf(mn.x, v.x); mn.y = fminf(mn.y, v.y);
        mn.z = fminf(mn.z, v.z); mn.w = fminf(mn.w, v.w);
    }
    int c = cg*4;
    float4 r;
    {
        float s0=g_sc2[c+0], s1=g_sc2[c+1], s2=g_sc2[c+2], s3=g_sc2[c+3];
        float h0=g_sh2[c+0], h1=g_sh2[c+1], h2=g_sh2[c+2], h3=g_sh2[c+3];
        r.x = fmaxf(0.f, fmaf(s0 >= 0.f ? mx.x : mn.x, s0, h0));
        r.y = fmaxf(0.f, fmaf(s1 >= 0.f ? mx.y : mn.y, s1, h1));
        r.z = fmaxf(0.f, fmaf(s2 >= 0.f ? mx.z : mn.z, s2, h2));
        r.w = fmaxf(0.f, fmaf(s3 >= 0.f ? mx.w : mn.w, s3, h3));
    }
    *(float4*)(out + NEWPOS_ELEMS + (size_t)row*CO + c) = r;
}

// ---------------- launch ----------------
extern "C" void kernel_launch(void* const* d_in, const int* in_sizes, int n_in,
                              void* d_out, int out_size)
{
    const float* pos    = (const float*)d_in[0];
    const float* points = (const float*)d_in[1];
    const int*   idx    = (const int*)  d_in[2];
    const float* W1     = (const float*)d_in[3];
    const float* b1     = (const float*)d_in[4];
    const float* g1     = (const float*)d_in[5];
    const float* beta1  = (const float*)d_in[6];
    const float* W2     = (const float*)d_in[7];
    const float* b2     = (const float*)d_in[8];
    const float* g2     = (const float*)d_in[9];
    const float* beta2  = (const float*)d_in[10];
    float* out = (float*)d_out;

    float *pP, *pH1, *pH2, *pSum1, *pSq1, *pSum2, *pSq2, *pSc1, *pSh1, *pSc2, *pSh2;
    cudaGetSymbolAddress((void**)&pP,   g_P);
    cudaGetSymbolAddress((void**)&pH1,  g_h1);
    cudaGetSymbolAddress((void**)&pH2,  g_h2);
    cudaGetSymbolAddress((void**)&pSum1,g_sum1);
    cudaGetSymbolAddress((void**)&pSq1, g_sumsq1);
    cudaGetSymbolAddress((void**)&pSum2,g_sum2);
    cudaGetSymbolAddress((void**)&pSq2, g_sumsq2);
    cudaGetSymbolAddress((void**)&pSc1, g_sc1);
    cudaGetSymbolAddress((void**)&pSh1, g_sh1);
    cudaGetSymbolAddress((void**)&pSc2, g_sc2);
    cudaGetSymbolAddress((void**)&pSh2, g_sh2);

    zero_stats_kernel<<<1, 256>>>();

    // kNN + new_pos output
    knn_kernel<<<QTOT/128, 128>>>(pos, idx, out);

    // P = points @ W1p^T   (A: [65536,128], B: W1 rows, cols 3..130)
    gemm_kernel<false, false, false><<<dim3((BB*NN)/128, CO/128), 256>>>(
        points, CC, W1, CI1, 3, pP, CC,
        nullptr, nullptr, nullptr, nullptr, nullptr);

    // h1 = P[knn] + W1r*rel + b1   (+ stats1)
    assemble_h1_kernel<<<ROWS/64, 256>>>(pos, idx, W1, b1);

    finalize_bn_kernel<<<1, 256>>>(pSum1, pSq1, g1, beta1, pSc1, pSh1);

    // h2 = relu(bn1(h1)) @ W2^T + b2   (+ stats2)
    gemm_kernel<true, true, true><<<dim3(ROWS/128, CO/128), 256>>>(
        pH1, CO, W2, CO, 0, pH2, CO,
        pSc1, pSh1, b2, pSum2, pSq2);

    finalize_bn_kernel<<<1, 256>>>(pSum2, pSq2, g2, beta2, pSc2, pSh2);

    // out new_points = relu(bn2(max/min_k h2))
    maxpool_kernel<<<(QTOT*64)/256, 256>>>(out);
}

// round 6
// speedup vs baseline: 1.6383x; 1.6370x over previous
#include <cuda_runtime.h>
#include <cuda_bf16.h>
#include <float.h>
#include <cstdint>

// Problem constants
#define BB   8
#define NN   8192
#define MM   4096
#define CC   128
#define KNN  16
#define CO   256          // output channels of both layers
#define CI1  131          // 3 + 128
#define ROWS (BB*MM*KNN)  // 524288
#define QTOT (BB*MM)      // 32768
#define NEWPOS_ELEMS (QTOT*3)   // 98304
#define NTILE (ROWS/128)        // 4096 M-tiles
#define NWORK (2*NTILE)         // 8192 work items (M-tile x N-half)

// ---------------- static scratch (allocation-free rule) ----------------
__device__ float g_P [ (size_t)BB*NN*CO ];       // 64 MB   points @ W1p^T
__device__ float g_h1[ (size_t)ROWS*CO ];        // 512 MB  layer1 pre-activations
__device__ float g_hmax[ (size_t)QTOT*CO ];      // 32 MB   max_k h2 (pre-BN2, +b2)
__device__ float g_hmin[ (size_t)QTOT*CO ];      // 32 MB   min_k h2
__device__ int   g_knn[ ROWS ];                  // 2 MB
__device__ __nv_bfloat16 g_Bhi[CO*CO];           // W2 split hi
__device__ __nv_bfloat16 g_Blo[CO*CO];           // W2 split lo
__device__ float g_sum1[CO], g_sumsq1[CO], g_sum2[CO], g_sumsq2[CO];
__device__ float g_sc1[CO], g_sh1[CO], g_sc2[CO], g_sh2[CO];

// ---------------- zero stats ----------------
__global__ void zero_stats_kernel() {
    int t = threadIdx.x;
    if (t < CO) { g_sum1[t]=0.f; g_sumsq1[t]=0.f; g_sum2[t]=0.f; g_sumsq2[t]=0.f; }
}

// ---------------- kNN (one thread per query, register top-16) ----------------
__global__ __launch_bounds__(128)
void knn_kernel(const float* __restrict__ pos, const int* __restrict__ idx,
                float* __restrict__ out_newpos)
{
    __shared__ float4 sp[2048];
    const int q = blockIdx.x * 128 + threadIdx.x;
    const int b = q >> 12;
    const float* pb = pos + (size_t)b * NN * 3;

    const int nq = idx[q];
    const float qx = pb[nq*3+0], qy = pb[nq*3+1], qz = pb[nq*3+2];
    out_newpos[q*3+0] = qx; out_newpos[q*3+1] = qy; out_newpos[q*3+2] = qz;
    const float qn = qx*qx + qy*qy + qz*qz;

    float dist[KNN]; int ind[KNN];
#pragma unroll
    for (int j = 0; j < KNN; j++) { dist[j] = FLT_MAX; ind[j] = 0x7fffffff; }
    float wd = FLT_MAX; int wi = 0x7fffffff, wj = 0;

    for (int c0 = 0; c0 < NN; c0 += 2048) {
        __syncthreads();
        for (int i = threadIdx.x; i < 2048; i += 128) {
            float x = pb[(c0+i)*3+0], y = pb[(c0+i)*3+1], z = pb[(c0+i)*3+2];
            sp[i] = make_float4(x, y, z, x*x + y*y + z*z);
        }
        __syncthreads();
#pragma unroll 4
        for (int i = 0; i < 2048; i++) {
            float4 p = sp[i];
            float qp = qx*p.x + qy*p.y + qz*p.z;
            float d  = qn - 2.0f*qp + p.w;
            if (d < wd) {
                int nidx = c0 + i;
#pragma unroll
                for (int j = 0; j < KNN; j++) if (j == wj) { dist[j] = d; ind[j] = nidx; }
                wd = dist[0]; wi = ind[0]; wj = 0;
#pragma unroll
                for (int j = 1; j < KNN; j++) {
                    if (dist[j] > wd || (dist[j] == wd && ind[j] > wi)) {
                        wd = dist[j]; wi = ind[j]; wj = j;
                    }
                }
            }
        }
    }
#pragma unroll
    for (int j = 0; j < KNN; j++) g_knn[q*KNN + j] = ind[j];
}

// ---------------- tiled SGEMM for P = points @ W1p^T ----------------
__global__ __launch_bounds__(256, 2)
void gemm_p_kernel(const float* __restrict__ A, int lda,
                   const float* __restrict__ Bw, int ldb, int boff,
                   float* __restrict__ C, int Kdim)
{
    const int BM = 128, BN = 128, BK = 16;
    __shared__ float As[BK][BM];
    __shared__ float Bs[BK][BN];

    const int t  = threadIdx.x;
    const int tx = t & 15, ty = t >> 4;
    const int rowBase = blockIdx.x * BM;
    const int colBase = blockIdx.y * BN;

    float acc[8][8];
#pragma unroll
    for (int i = 0; i < 8; i++)
#pragma unroll
        for (int j = 0; j < 8; j++) acc[i][j] = 0.f;

    for (int k0 = 0; k0 < Kdim; k0 += BK) {
#pragma unroll
        for (int l = 0; l < 2; l++) {
            int fid = t + l*256;
            int row = fid >> 2, c4 = (fid & 3) * 4;
            float4 v = *(const float4*)(A + (size_t)(rowBase + row)*lda + k0 + c4);
            As[c4+0][row] = v.x; As[c4+1][row] = v.y;
            As[c4+2][row] = v.z; As[c4+3][row] = v.w;
        }
#pragma unroll
        for (int l = 0; l < 8; l++) {
            int e = t + l*256;
            int c = e & 15, o = e >> 4;
            Bs[c][o] = Bw[(size_t)(colBase + o)*ldb + boff + k0 + c];
        }
        __syncthreads();
#pragma unroll
        for (int kk = 0; kk < BK; kk++) {
            float4 a0 = *(const float4*)&As[kk][ty*8];
            float4 a1 = *(const float4*)&As[kk][ty*8+4];
            float4 b0 = *(const float4*)&Bs[kk][tx*8];
            float4 b1 = *(const float4*)&Bs[kk][tx*8+4];
            float aR[8] = {a0.x,a0.y,a0.z,a0.w,a1.x,a1.y,a1.z,a1.w};
            float bR[8] = {b0.x,b0.y,b0.z,b0.w,b1.x,b1.y,b1.z,b1.w};
#pragma unroll
            for (int i = 0; i < 8; i++)
#pragma unroll
                for (int j = 0; j < 8; j++)
                    acc[i][j] = fmaf(aR[i], bR[j], acc[i][j]);
        }
        __syncthreads();
    }
#pragma unroll
    for (int i = 0; i < 8; i++) {
        int row = rowBase + ty*8 + i;
        float* cp = C + (size_t)row*CO + colBase + tx*8;
        *(float4*)cp       = make_float4(acc[i][0], acc[i][1], acc[i][2], acc[i][3]);
        *(float4*)(cp + 4) = make_float4(acc[i][4], acc[i][5], acc[i][6], acc[i][7]);
    }
}

// ---------------- assemble h1 = P[knn] + W1r*rel + b1  (+ stats) ----------------
__global__ __launch_bounds__(256)
void assemble_h1_kernel(const float* __restrict__ pos, const int* __restrict__ idx,
                        const float* __restrict__ W1, const float* __restrict__ b1)
{
    const int RPB = 64;
    __shared__ int   s_pb[RPB];
    __shared__ float s_r[RPB][3];
    const int base = blockIdx.x * RPB;
    const int t = threadIdx.x;
    if (t < RPB) {
        int r  = base + t;
        int b  = r >> 16;
        int m  = (r >> 4) & 4095;
        int nn = g_knn[r];
        const float* pb = pos + (size_t)b * NN * 3;
        int nq = idx[b*MM + m];
        s_r[t][0] = pb[nn*3+0] - pb[nq*3+0];
        s_r[t][1] = pb[nn*3+1] - pb[nq*3+1];
        s_r[t][2] = pb[nn*3+2] - pb[nq*3+2];
        s_pb[t]   = (b*NN + nn) * CO;
    }
    __syncthreads();
    const int o = t;
    const float w0 = W1[o*CI1+0], w1 = W1[o*CI1+1], w2 = W1[o*CI1+2], bb = b1[o];
    float ls = 0.f, lss = 0.f;
#pragma unroll 4
    for (int rr = 0; rr < RPB; rr++) {
        float v = g_P[(size_t)s_pb[rr] + o];
        v = v + bb + w0*s_r[rr][0] + w1*s_r[rr][1] + w2*s_r[rr][2];
        g_h1[(size_t)(base + rr)*CO + o] = v;
        ls += v; lss += v*v;
    }
    atomicAdd(&g_sum1[o], ls);
    atomicAdd(&g_sumsq1[o], lss);
}

// ---------------- finalize BN ----------------
__global__ void finalize_bn_kernel(const float* __restrict__ sum, const float* __restrict__ sq,
                                   const float* __restrict__ g,   const float* __restrict__ beta,
                                   float* __restrict__ sc, float* __restrict__ sh)
{
    int o = threadIdx.x;
    const float inv = 1.0f / (float)ROWS;
    float mean = sum[o] * inv;
    float var  = sq[o] * inv - mean*mean;
    float rstd = rsqrtf(var + 1e-5f);
    float s = g[o] * rstd;
    sc[o] = s;
    sh[o] = fmaf(-mean, s, beta[o]);
}

// ---------------- split W2 into bf16 hi/lo ----------------
__global__ void split_w2_kernel(const float* __restrict__ W2) {
    int i = blockIdx.x * 256 + threadIdx.x;     // 65536 total
    float v = W2[i];
    __nv_bfloat16 h = __float2bfloat16(v);
    g_Bhi[i] = h;
    g_Blo[i] = __float2bfloat16(v - __bfloat162float(h));
}

// ================= GEMM2 via mma.sync bf16 (3-term split) =================
// SMEM map (dynamic):
//   [0,1024)        s_sc (BN1 scale)
//   [1024,2048)     s_sh (BN1 shift)
//   [2048,+67584)   B hi: 128 rows x 264 bf16 (pad 8) = 528 B/row
//   [69632,+67584)  B lo
//   [137216,+10240) A hi: 128 rows x 40 bf16 (32 + pad 8) = 80 B/row
//   [147456,+10240) A lo
#define SM2_BHI  2048
#define SM2_BLO  (SM2_BHI + 67584)
#define SM2_AHI  (SM2_BLO + 67584)
#define SM2_ALO  (SM2_AHI + 10240)
#define SMEM_G2  (SM2_ALO + 10240)     // 157696 bytes

__device__ __forceinline__ void mma16816(float* c, const uint32_t* a,
                                         uint32_t b0, uint32_t b1) {
    asm volatile(
        "mma.sync.aligned.m16n8k16.row.col.f32.bf16.bf16.f32 "
        "{%0,%1,%2,%3}, {%4,%5,%6,%7}, {%8,%9}, {%0,%1,%2,%3};\n"
        : "+f"(c[0]), "+f"(c[1]), "+f"(c[2]), "+f"(c[3])
        : "r"(a[0]), "r"(a[1]), "r"(a[2]), "r"(a[3]), "r"(b0), "r"(b1));
}
__device__ __forceinline__ uint32_t pack_bf2(__nv_bfloat16 a, __nv_bfloat16 b) {
    return (uint32_t)__bfloat16_as_ushort(a) | ((uint32_t)__bfloat16_as_ushort(b) << 16);
}

__global__ __launch_bounds__(256, 1)
void gemm2_mma_kernel(const float* __restrict__ b2)
{
    extern __shared__ char smx[];
    float* s_sc = (float*)(smx);
    float* s_sh = (float*)(smx + 1024);
    char*  sBhi = smx + SM2_BHI;
    char*  sBlo = smx + SM2_BLO;
    char*  sAhi = smx + SM2_AHI;
    char*  sAlo = smx + SM2_ALO;

    const int t    = threadIdx.x;
    const int lane = t & 31, wid = t >> 5;
    const int warp_m = wid & 1;         // 0..1  -> 64-row half
    const int warp_n = wid >> 1;        // 0..3  -> 32-col slice
    const int nh   = blockIdx.x & 1;    // N-half (stride 148 is even -> fixed)

    s_sc[t] = g_sc1[t];
    s_sh[t] = g_sh1[t];

    // resident B half (hi/lo): 128 rows x 256 ch, padded rows of 528 B
    // e = 0..4095 -> n = e>>5 (0..127), k8 = e&31 (0..31), 8 bf16 per uint4
#pragma unroll
    for (int l = 0; l < 16; l++) {
        int e = t + l*256;
        int n = e >> 5, k8 = e & 31;
        size_t gsrc = ((size_t)(nh*128 + n))*CO + k8*8;
        *(uint4*)(sBhi + n*528 + k8*16) = *(const uint4*)(g_Bhi + gsrc);
        *(uint4*)(sBlo + n*528 + k8*16) = *(const uint4*)(g_Blo + gsrc);
    }

    // per-thread bias + stats registers (cols fixed for this thread)
    float b2v[4][2], st_s[4][2], st_q[4][2];
    const int colb = nh*128 + warp_n*32 + 2*(lane & 3);
#pragma unroll
    for (int j = 0; j < 4; j++) {
        b2v[j][0] = b2[colb + j*8];
        b2v[j][1] = b2[colb + j*8 + 1];
        st_s[j][0] = st_s[j][1] = 0.f;
        st_q[j][0] = st_q[j][1] = 0.f;
    }

    const int qrow  = t >> 1;           // loader row 0..127
    const int khalf = (t & 1) * 16;     // loader k-offset within 32-chunk

    for (int wi = blockIdx.x; wi < NWORK; wi += gridDim.x) {
        const int mtile = wi >> 1;
        const size_t rowBase = (size_t)mtile * 128;

        float acc[4][4][4];
#pragma unroll
        for (int i = 0; i < 4; i++)
#pragma unroll
            for (int j = 0; j < 4; j++)
#pragma unroll
                for (int d = 0; d < 4; d++) acc[i][j][d] = 0.f;

        // prefetch chunk 0 into registers
        float4 pf[4];
        {
            const float4* src = (const float4*)(g_h1 + (rowBase + qrow)*CO + khalf);
            pf[0] = src[0]; pf[1] = src[1]; pf[2] = src[2]; pf[3] = src[3];
        }

        for (int c = 0; c < 8; c++) {
            __syncthreads();   // smem A free (all warps done with previous chunk/tile)
            // store prefetched chunk -> smem with BN1+ReLU + hi/lo split
            {
                char* aH = sAhi + qrow*80 + khalf*2;
                char* aL = sAlo + qrow*80 + khalf*2;
                const int cb = c*32 + khalf;
#pragma unroll
                for (int v = 0; v < 4; v++) {
                    float4 f = pf[v];
                    int ch = cb + v*4;
                    float x0 = fmaxf(0.f, fmaf(f.x, s_sc[ch+0], s_sh[ch+0]));
                    float x1 = fmaxf(0.f, fmaf(f.y, s_sc[ch+1], s_sh[ch+1]));
                    float x2 = fmaxf(0.f, fmaf(f.z, s_sc[ch+2], s_sh[ch+2]));
                    float x3 = fmaxf(0.f, fmaf(f.w, s_sc[ch+3], s_sh[ch+3]));
                    __nv_bfloat16 h0 = __float2bfloat16(x0), h1 = __float2bfloat16(x1);
                    __nv_bfloat16 h2 = __float2bfloat16(x2), h3 = __float2bfloat16(x3);
                    __nv_bfloat16 l0 = __float2bfloat16(x0 - __bfloat162float(h0));
                    __nv_bfloat16 l1 = __float2bfloat16(x1 - __bfloat162float(h1));
                    __nv_bfloat16 l2 = __float2bfloat16(x2 - __bfloat162float(h2));
                    __nv_bfloat16 l3 = __float2bfloat16(x3 - __bfloat162float(h3));
                    uint2 ph = make_uint2(pack_bf2(h0,h1), pack_bf2(h2,h3));
                    uint2 pl = make_uint2(pack_bf2(l0,l1), pack_bf2(l2,l3));
                    *(uint2*)(aH + v*8) = ph;
                    *(uint2*)(aL + v*8) = pl;
                }
            }
            // prefetch next chunk (LDG latency overlaps mma below)
            if (c < 7) {
                const float4* src = (const float4*)(g_h1 + (rowBase + qrow)*CO
                                                    + (c+1)*32 + khalf);
                pf[0] = src[0]; pf[1] = src[1]; pf[2] = src[2]; pf[3] = src[3];
            }
            __syncthreads();   // smem A ready

            // two k16 steps over this 32-wide chunk
#pragma unroll
            for (int ks = 0; ks < 2; ks++) {
                uint32_t aH[4][4], aL[4][4];
#pragma unroll
                for (int i = 0; i < 4; i++) {
                    int m = warp_m*64 + i*16 + (lane >> 2);
                    const char* p  = sAhi + m*80 + ks*32 + (lane & 3)*4;
                    const char* pl = sAlo + m*80 + ks*32 + (lane & 3)*4;
                    aH[i][0] = *(const uint32_t*)(p);
                    aH[i][1] = *(const uint32_t*)(p + 640);
                    aH[i][2] = *(const uint32_t*)(p + 16);
                    aH[i][3] = *(const uint32_t*)(p + 656);
                    aL[i][0] = *(const uint32_t*)(pl);
                    aL[i][1] = *(const uint32_t*)(pl + 640);
                    aL[i][2] = *(const uint32_t*)(pl + 16);
                    aL[i][3] = *(const uint32_t*)(pl + 656);
                }
#pragma unroll
                for (int j = 0; j < 4; j++) {
                    int n = warp_n*32 + j*8 + (lane >> 2);
                    const char* pb  = sBhi + n*528 + (c*32 + ks*16)*2 + (lane & 3)*4;
                    const char* pbl = sBlo + n*528 + (c*32 + ks*16)*2 + (lane & 3)*4;
                    uint32_t bh0 = *(const uint32_t*)pb;
                    uint32_t bh1 = *(const uint32_t*)(pb + 16);
                    uint32_t bl0 = *(const uint32_t*)pbl;
                    uint32_t bl1 = *(const uint32_t*)(pbl + 16);
#pragma unroll
                    for (int i = 0; i < 4; i++) {
                        mma16816(acc[i][j], aH[i], bh0, bh1);
                        mma16816(acc[i][j], aL[i], bh0, bh1);
                        mma16816(acc[i][j], aH[i], bl0, bl1);
                    }
                }
            }
        }

        // ---- fused epilogue: bias + stats + 16-row max/min pool via shuffles ----
#pragma unroll
        for (int i = 0; i < 4; i++) {
            int q = mtile*8 + warp_m*4 + i;
#pragma unroll
            for (int j = 0; j < 4; j++) {
                float v0 = acc[i][j][0] + b2v[j][0];
                float v1 = acc[i][j][1] + b2v[j][1];
                float v2 = acc[i][j][2] + b2v[j][0];
                float v3 = acc[i][j][3] + b2v[j][1];
                st_s[j][0] += v0 + v2;
                st_q[j][0] += v0*v0 + v2*v2;
                st_s[j][1] += v1 + v3;
                st_q[j][1] += v1*v1 + v3*v3;
                float mx0 = fmaxf(v0, v2), mn0 = fminf(v0, v2);
                float mx1 = fmaxf(v1, v3), mn1 = fminf(v1, v3);
#pragma unroll
                for (int s = 4; s <= 16; s <<= 1) {
                    mx0 = fmaxf(mx0, __shfl_xor_sync(0xffffffffu, mx0, s));
                    mn0 = fminf(mn0, __shfl_xor_sync(0xffffffffu, mn0, s));
                    mx1 = fmaxf(mx1, __shfl_xor_sync(0xffffffffu, mx1, s));
                    mn1 = fminf(mn1, __shfl_xor_sync(0xffffffffu, mn1, s));
                }
                if (lane < 4) {
                    int col = nh*128 + warp_n*32 + j*8 + 2*lane;
                    g_hmax[(size_t)q*CO + col]     = mx0;
                    g_hmax[(size_t)q*CO + col + 1] = mx1;
                    g_hmin[(size_t)q*CO + col]     = mn0;
                    g_hmin[(size_t)q*CO + col + 1] = mn1;
                }
            }
        }
    }

    // flush BN2 stats (8 columns per thread, partial over this thread's rows)
#pragma unroll
    for (int j = 0; j < 4; j++) {
        atomicAdd(&g_sum2  [colb + j*8],     st_s[j][0]);
        atomicAdd(&g_sumsq2[colb + j*8],     st_q[j][0]);
        atomicAdd(&g_sum2  [colb + j*8 + 1], st_s[j][1]);
        atomicAdd(&g_sumsq2[colb + j*8 + 1], st_q[j][1]);
    }
}

// ---------------- final: out = relu(bn2(max-or-min)) ----------------
__global__ __launch_bounds__(256)
void final_out_kernel(float* __restrict__ out)
{
    int t = blockIdx.x * 256 + threadIdx.x;       // 0 .. QTOT*64
    int row = t >> 6, cg = t & 63;
    int c = cg * 4;
    float4 mx = *(const float4*)(g_hmax + (size_t)row*CO + c);
    float4 mn = *(const float4*)(g_hmin + (size_t)row*CO + c);
    float s0 = g_sc2[c+0], s1 = g_sc2[c+1], s2 = g_sc2[c+2], s3 = g_sc2[c+3];
    float h0 = g_sh2[c+0], h1 = g_sh2[c+1], h2 = g_sh2[c+2], h3 = g_sh2[c+3];
    float4 r;
    r.x = fmaxf(0.f, fmaf(s0 >= 0.f ? mx.x : mn.x, s0, h0));
    r.y = fmaxf(0.f, fmaf(s1 >= 0.f ? mx.y : mn.y, s1, h1));
    r.z = fmaxf(0.f, fmaf(s2 >= 0.f ? mx.z : mn.z, s2, h2));
    r.w = fmaxf(0.f, fmaf(s3 >= 0.f ? mx.w : mn.w, s3, h3));
    *(float4*)(out + NEWPOS_ELEMS + (size_t)row*CO + c) = r;
}

// ---------------- launch ----------------
extern "C" void kernel_launch(void* const* d_in, const int* in_sizes, int n_in,
                              void* d_out, int out_size)
{
    const float* pos    = (const float*)d_in[0];
    const float* points = (const float*)d_in[1];
    const int*   idx    = (const int*)  d_in[2];
    const float* W1     = (const float*)d_in[3];
    const float* b1     = (const float*)d_in[4];
    const float* g1     = (const float*)d_in[5];
    const float* beta1  = (const float*)d_in[6];
    const float* W2     = (const float*)d_in[7];
    const float* b2     = (const float*)d_in[8];
    const float* g2     = (const float*)d_in[9];
    const float* beta2  = (const float*)d_in[10];
    float* out = (float*)d_out;

    float *pP, *pSum1, *pSq1, *pSum2, *pSq2, *pSc1, *pSh1, *pSc2, *pSh2;
    cudaGetSymbolAddress((void**)&pP,   g_P);
    cudaGetSymbolAddress((void**)&pSum1,g_sum1);
    cudaGetSymbolAddress((void**)&pSq1, g_sumsq1);
    cudaGetSymbolAddress((void**)&pSum2,g_sum2);
    cudaGetSymbolAddress((void**)&pSq2, g_sumsq2);
    cudaGetSymbolAddress((void**)&pSc1, g_sc1);
    cudaGetSymbolAddress((void**)&pSh1, g_sh1);
    cudaGetSymbolAddress((void**)&pSc2, g_sc2);
    cudaGetSymbolAddress((void**)&pSh2, g_sh2);

    cudaFuncSetAttribute(gemm2_mma_kernel,
                         cudaFuncAttributeMaxDynamicSharedMemorySize, SMEM_G2);

    zero_stats_kernel<<<1, 256>>>();
    knn_kernel<<<QTOT/128, 128>>>(pos, idx, out);
    split_w2_kernel<<<CO*CO/256, 256>>>(W2);

    gemm_p_kernel<<<dim3((BB*NN)/128, CO/128), 256>>>(points, CC, W1, CI1, 3, pP, CC);

    assemble_h1_kernel<<<ROWS/64, 256>>>(pos, idx, W1, b1);
    finalize_bn_kernel<<<1, 256>>>(pSum1, pSq1, g1, beta1, pSc1, pSh1);

    gemm2_mma_kernel<<<148, 256, SMEM_G2>>>(b2);

    finalize_bn_kernel<<<1, 256>>>(pSum2, pSq2, g2, beta2, pSc2, pSh2);
    final_out_kernel<<<(QTOT*64)/256, 256>>>(out);
}

// round 10
// speedup vs baseline: 1.6750x; 1.0224x over previous
#include <cuda_runtime.h>
#include <cuda_bf16.h>
#include <float.h>
#include <cstdint>

// Problem constants
#define BB   8
#define NN   8192
#define MM   4096
#define CC   128
#define KNN  16
#define CO   256          // output channels of both layers
#define CI1  131          // 3 + 128
#define ROWS (BB*MM*KNN)  // 524288
#define QTOT (BB*MM)      // 32768
#define NEWPOS_ELEMS (QTOT*3)   // 98304
#define NTILE (ROWS/128)        // 4096 M-tiles
#define NWORK (2*NTILE)         // 8192 work items (M-tile x N-half)

// ---------------- static scratch (allocation-free rule) ----------------
__device__ float g_P [ (size_t)BB*NN*CO ];       // 64 MB   points @ W1p^T
__device__ float g_h1[ (size_t)ROWS*CO ];        // 512 MB  layer1 pre-activations
__device__ float g_hmax[ (size_t)QTOT*CO ];      // 32 MB   max_k h2 (pre-BN2, +b2)
__device__ float g_hmin[ (size_t)QTOT*CO ];      // 32 MB   min_k h2
__device__ int   g_knn[ ROWS ];                  // 2 MB
__device__ __nv_bfloat16 g_Bhi[CO*CO];           // W2 split hi
__device__ __nv_bfloat16 g_Blo[CO*CO];           // W2 split lo
__device__ float g_sum1[CO], g_sumsq1[CO], g_sum2[CO], g_sumsq2[CO];
__device__ float g_sc1[CO], g_sh1[CO], g_sc2[CO], g_sh2[CO];

// ---------------- zero stats ----------------
__global__ void zero_stats_kernel() {
    int t = threadIdx.x;
    if (t < CO) { g_sum1[t]=0.f; g_sumsq1[t]=0.f; g_sum2[t]=0.f; g_sumsq2[t]=0.f; }
}

// ---------------- kNN (one thread per query, register top-16) ----------------
__global__ __launch_bounds__(128)
void knn_kernel(const float* __restrict__ pos, const int* __restrict__ idx,
                float* __restrict__ out_newpos)
{
    __shared__ float4 sp[2048];
    const int q = blockIdx.x * 128 + threadIdx.x;
    const int b = q >> 12;
    const float* pb = pos + (size_t)b * NN * 3;

    const int nq = idx[q];
    const float qx = pb[nq*3+0], qy = pb[nq*3+1], qz = pb[nq*3+2];
    out_newpos[q*3+0] = qx; out_newpos[q*3+1] = qy; out_newpos[q*3+2] = qz;
    const float qn = qx*qx + qy*qy + qz*qz;

    float dist[KNN]; int ind[KNN];
#pragma unroll
    for (int j = 0; j < KNN; j++) { dist[j] = FLT_MAX; ind[j] = 0x7fffffff; }
    float wd = FLT_MAX; int wi = 0x7fffffff, wj = 0;

    for (int c0 = 0; c0 < NN; c0 += 2048) {
        __syncthreads();
        for (int i = threadIdx.x; i < 2048; i += 128) {
            float x = pb[(c0+i)*3+0], y = pb[(c0+i)*3+1], z = pb[(c0+i)*3+2];
            sp[i] = make_float4(x, y, z, x*x + y*y + z*z);
        }
        __syncthreads();
#pragma unroll 4
        for (int i = 0; i < 2048; i++) {
            float4 p = sp[i];
            float qp = qx*p.x + qy*p.y + qz*p.z;
            float d  = qn - 2.0f*qp + p.w;
            if (d < wd) {
                int nidx = c0 + i;
#pragma unroll
                for (int j = 0; j < KNN; j++) if (j == wj) { dist[j] = d; ind[j] = nidx; }
                wd = dist[0]; wi = ind[0]; wj = 0;
#pragma unroll
                for (int j = 1; j < KNN; j++) {
                    if (dist[j] > wd || (dist[j] == wd && ind[j] > wi)) {
                        wd = dist[j]; wi = ind[j]; wj = j;
                    }
                }
            }
        }
    }
#pragma unroll
    for (int j = 0; j < KNN; j++) g_knn[q*KNN + j] = ind[j];
}

// ---------------- tiled SGEMM for P = points @ W1p^T ----------------
__global__ __launch_bounds__(256, 2)
void gemm_p_kernel(const float* __restrict__ A, int lda,
                   const float* __restrict__ Bw, int ldb, int boff,
                   float* __restrict__ C, int Kdim)
{
    const int BM = 128, BN = 128, BK = 16;
    __shared__ float As[BK][BM];
    __shared__ float Bs[BK][BN];

    const int t  = threadIdx.x;
    const int tx = t & 15, ty = t >> 4;
    const int rowBase = blockIdx.x * BM;
    const int colBase = blockIdx.y * BN;

    float acc[8][8];
#pragma unroll
    for (int i = 0; i < 8; i++)
#pragma unroll
        for (int j = 0; j < 8; j++) acc[i][j] = 0.f;

    for (int k0 = 0; k0 < Kdim; k0 += BK) {
#pragma unroll
        for (int l = 0; l < 2; l++) {
            int fid = t + l*256;
            int row = fid >> 2, c4 = (fid & 3) * 4;
            float4 v = *(const float4*)(A + (size_t)(rowBase + row)*lda + k0 + c4);
            As[c4+0][row] = v.x; As[c4+1][row] = v.y;
            As[c4+2][row] = v.z; As[c4+3][row] = v.w;
        }
#pragma unroll
        for (int l = 0; l < 8; l++) {
            int e = t + l*256;
            int c = e & 15, o = e >> 4;
            Bs[c][o] = Bw[(size_t)(colBase + o)*ldb + boff + k0 + c];
        }
        __syncthreads();
#pragma unroll
        for (int kk = 0; kk < BK; kk++) {
            float4 a0 = *(const float4*)&As[kk][ty*8];
            float4 a1 = *(const float4*)&As[kk][ty*8+4];
            float4 b0 = *(const float4*)&Bs[kk][tx*8];
            float4 b1 = *(const float4*)&Bs[kk][tx*8+4];
            float aR[8] = {a0.x,a0.y,a0.z,a0.w,a1.x,a1.y,a1.z,a1.w};
            float bR[8] = {b0.x,b0.y,b0.z,b0.w,b1.x,b1.y,b1.z,b1.w};
#pragma unroll
            for (int i = 0; i < 8; i++)
#pragma unroll
                for (int j = 0; j < 8; j++)
                    acc[i][j] = fmaf(aR[i], bR[j], acc[i][j]);
        }
        __syncthreads();
    }
#pragma unroll
    for (int i = 0; i < 8; i++) {
        int row = rowBase + ty*8 + i;
        float* cp = C + (size_t)row*CO + colBase + tx*8;
        *(float4*)cp       = make_float4(acc[i][0], acc[i][1], acc[i][2], acc[i][3]);
        *(float4*)(cp + 4) = make_float4(acc[i][4], acc[i][5], acc[i][6], acc[i][7]);
    }
}

// ---------------- assemble h1 = P[knn] + W1r*rel + b1  (+ stats) ----------------
__global__ __launch_bounds__(256)
void assemble_h1_kernel(const float* __restrict__ pos, const int* __restrict__ idx,
                        const float* __restrict__ W1, const float* __restrict__ b1)
{
    const int RPB = 64;
    __shared__ int   s_pb[RPB];
    __shared__ float s_r[RPB][3];
    const int base = blockIdx.x * RPB;
    const int t = threadIdx.x;
    if (t < RPB) {
        int r  = base + t;
        int b  = r >> 16;
        int m  = (r >> 4) & 4095;
        int nn = g_knn[r];
        const float* pb = pos + (size_t)b * NN * 3;
        int nq = idx[b*MM + m];
        s_r[t][0] = pb[nn*3+0] - pb[nq*3+0];
        s_r[t][1] = pb[nn*3+1] - pb[nq*3+1];
        s_r[t][2] = pb[nn*3+2] - pb[nq*3+2];
        s_pb[t]   = (b*NN + nn) * CO;
    }
    __syncthreads();
    const int o = t;
    const float w0 = W1[o*CI1+0], w1 = W1[o*CI1+1], w2 = W1[o*CI1+2], bb = b1[o];
    float ls = 0.f, lss = 0.f;
#pragma unroll 4
    for (int rr = 0; rr < RPB; rr++) {
        float v = g_P[(size_t)s_pb[rr] + o];
        v = v + bb + w0*s_r[rr][0] + w1*s_r[rr][1] + w2*s_r[rr][2];
        g_h1[(size_t)(base + rr)*CO + o] = v;
        ls += v; lss += v*v;
    }
    atomicAdd(&g_sum1[o], ls);
    atomicAdd(&g_sumsq1[o], lss);
}

// ---------------- finalize BN ----------------
__global__ void finalize_bn_kernel(const float* __restrict__ sum, const float* __restrict__ sq,
                                   const float* __restrict__ g,   const float* __restrict__ beta,
                                   float* __restrict__ sc, float* __restrict__ sh)
{
    int o = threadIdx.x;
    const float inv = 1.0f / (float)ROWS;
    float mean = sum[o] * inv;
    float var  = sq[o] * inv - mean*mean;
    float rstd = rsqrtf(var + 1e-5f);
    float s = g[o] * rstd;
    sc[o] = s;
    sh[o] = fmaf(-mean, s, beta[o]);
}

// ---------------- split W2 into bf16 hi/lo ----------------
__global__ void split_w2_kernel(const float* __restrict__ W2) {
    int i = blockIdx.x * 256 + threadIdx.x;     // 65536 total
    float v = W2[i];
    __nv_bfloat16 h = __float2bfloat16(v);
    g_Bhi[i] = h;
    g_Blo[i] = __float2bfloat16(v - __bfloat162float(h));
}

// ================= GEMM2 via mma.sync bf16 (3-term split) + ldmatrix ========
// SMEM map (dynamic):
//   [0,1024)        s_sc (BN1 scale)
//   [1024,2048)     s_sh (BN1 shift)
//   [2048,+67584)   B hi: 128 rows x 264 bf16 (pad 8) = 528 B/row
//   [69632,+67584)  B lo
//   [137216,+40960) A double-buffered: buf{0,1} x {hi,lo}, each 128 rows x 80 B
#define SM2_BHI  2048
#define SM2_BLO  (SM2_BHI + 67584)
#define SM2_A    (SM2_BLO + 67584)      // 137216
#define SM2_ABUF 20480                  // one buffer = hi(10240) + lo(10240)
#define SMEM_G2  (SM2_A + 2*SM2_ABUF)   // 178176 bytes

__device__ __forceinline__ void mma16816(float* c, const uint32_t* a,
                                         uint32_t b0, uint32_t b1) {
    asm volatile(
        "mma.sync.aligned.m16n8k16.row.col.f32.bf16.bf16.f32 "
        "{%0,%1,%2,%3}, {%4,%5,%6,%7}, {%8,%9}, {%0,%1,%2,%3};\n"
        : "+f"(c[0]), "+f"(c[1]), "+f"(c[2]), "+f"(c[3])
        : "r"(a[0]), "r"(a[1]), "r"(a[2]), "r"(a[3]), "r"(b0), "r"(b1));
}
__device__ __forceinline__ void ldsm_x4(uint32_t* r, uint32_t addr) {
    asm volatile("ldmatrix.sync.aligned.m8n8.x4.shared.b16 {%0,%1,%2,%3}, [%4];"
                 : "=r"(r[0]), "=r"(r[1]), "=r"(r[2]), "=r"(r[3]) : "r"(addr));
}
__device__ __forceinline__ uint32_t pack_bf2(__nv_bfloat16 a, __nv_bfloat16 b) {
    return (uint32_t)__bfloat16_as_ushort(a) | ((uint32_t)__bfloat16_as_ushort(b) << 16);
}

__global__ __launch_bounds__(256, 1)
void gemm2_mma_kernel(const float* __restrict__ b2)
{
    extern __shared__ char smx[];
    float* s_sc = (float*)(smx);
    float* s_sh = (float*)(smx + 1024);
    char*  sBhi = smx + SM2_BHI;
    char*  sBlo = smx + SM2_BLO;

    const int t    = threadIdx.x;
    const int lane = t & 31, wid = t >> 5;
    const int warp_m = wid & 1;         // 0..1  -> 64-row half
    const int warp_n = wid >> 1;        // 0..3  -> 32-col slice
    const int nh   = blockIdx.x & 1;    // N-half (grid stride even -> fixed)

    const uint32_t smemBase = (uint32_t)__cvta_generic_to_shared(smx);

    s_sc[t] = g_sc1[t];
    s_sh[t] = g_sh1[t];

    // resident B half (hi/lo): 128 rows x 256 ch, padded rows of 528 B
#pragma unroll
    for (int l = 0; l < 16; l++) {
        int e = t + l*256;
        int n = e >> 5, k8 = e & 31;
        size_t gsrc = ((size_t)(nh*128 + n))*CO + k8*8;
        *(uint4*)(sBhi + n*528 + k8*16) = *(const uint4*)(g_Bhi + gsrc);
        *(uint4*)(sBlo + n*528 + k8*16) = *(const uint4*)(g_Blo + gsrc);
    }

    // per-thread bias + stats registers (cols fixed for this thread)
    float b2v[4][2], st_s[4][2], st_q[4][2];
    const int colb = nh*128 + warp_n*32 + 2*(lane & 3);
#pragma unroll
    for (int j = 0; j < 4; j++) {
        b2v[j][0] = b2[colb + j*8];
        b2v[j][1] = b2[colb + j*8 + 1];
        st_s[j][0] = st_s[j][1] = 0.f;
        st_q[j][0] = st_q[j][1] = 0.f;
    }

    // ldmatrix lane-address bases
    // A x4 tiles (m16k16): lanes 0-7: (m0-7,k0) | 8-15: (m8-15,k0) | 16-23: (m0-7,k8) | 24-31: (m8-15,k8)
    const int aM = warp_m*64 + (lane & 7) + ((lane >> 3) & 1)*8;
    const uint32_t aLane = (uint32_t)(aM*80 + (lane >> 4)*16);
    const uint32_t aBase0 = smemBase + SM2_A + aLane;              // buf0 hi
    const uint32_t aBase1 = smemBase + SM2_A + SM2_ABUF + aLane;   // buf1 hi
    // B x4 tiles (two n8 slices x k16): lanes 0-7:(n0-7,k0) | 8-15:(n0-7,k8) | 16-23:(n8-15,k0) | 24-31:(n8-15,k8)
    const int bN = warp_n*32 + (lane & 7) + (lane >> 4)*8;
    const uint32_t bKoff = ((lane >> 3) & 1)*16;
    const uint32_t bLaneHi = smemBase + SM2_BHI + bN*528 + bKoff;
    const uint32_t bLaneLo = smemBase + SM2_BLO + bN*528 + bKoff;

    const int qrow  = t >> 1;           // loader row 0..127
    const int khalf = (t & 1) * 16;     // loader k-offset within 32-chunk

    __syncthreads();   // params + B resident visible before first use

    for (int wi = blockIdx.x; wi < NWORK; wi += gridDim.x) {
        const int mtile = wi >> 1;
        const size_t rowBase = (size_t)mtile * 128;

        float acc[4][4][4];
#pragma unroll
        for (int i = 0; i < 4; i++)
#pragma unroll
            for (int j = 0; j < 4; j++)
#pragma unroll
                for (int d = 0; d < 4; d++) acc[i][j][d] = 0.f;

        // prefetch chunk 0 into registers
        float4 pf[4];
        {
            const float4* src = (const float4*)(g_h1 + (rowBase + qrow)*CO + khalf);
            pf[0] = src[0]; pf[1] = src[1]; pf[2] = src[2]; pf[3] = src[3];
        }

#pragma unroll 2
        for (int c = 0; c < 8; c++) {
            const int buf = c & 1;
            // store prefetched chunk -> A buf with BN1+ReLU + hi/lo split
            {
                char* aH = smx + SM2_A + buf*SM2_ABUF + qrow*80 + khalf*2;
                char* aL = aH + 10240;
                const int cb = c*32 + khalf;
#pragma unroll
                for (int v = 0; v < 4; v++) {
                    float4 f = pf[v];
                    int ch = cb + v*4;
                    float x0 = fmaxf(0.f, fmaf(f.x, s_sc[ch+0], s_sh[ch+0]));
                    float x1 = fmaxf(0.f, fmaf(f.y, s_sc[ch+1], s_sh[ch+1]));
                    float x2 = fmaxf(0.f, fmaf(f.z, s_sc[ch+2], s_sh[ch+2]));
                    float x3 = fmaxf(0.f, fmaf(f.w, s_sc[ch+3], s_sh[ch+3]));
                    __nv_bfloat16 h0 = __float2bfloat16(x0), h1 = __float2bfloat16(x1);
                    __nv_bfloat16 h2 = __float2bfloat16(x2), h3 = __float2bfloat16(x3);
                    __nv_bfloat16 l0 = __float2bfloat16(x0 - __bfloat162float(h0));
                    __nv_bfloat16 l1 = __float2bfloat16(x1 - __bfloat162float(h1));
                    __nv_bfloat16 l2 = __float2bfloat16(x2 - __bfloat162float(h2));
                    __nv_bfloat16 l3 = __float2bfloat16(x3 - __bfloat162float(h3));
                    uint2 ph = make_uint2(pack_bf2(h0,h1), pack_bf2(h2,h3));
                    uint2 pl = make_uint2(pack_bf2(l0,l1), pack_bf2(l2,l3));
                    *(uint2*)(aH + v*8) = ph;
                    *(uint2*)(aL + v*8) = pl;
                }
            }
            // prefetch next chunk (LDG latency overlaps mma below)
            if (c < 7) {
                const float4* src = (const float4*)(g_h1 + (rowBase + qrow)*CO
                                                    + (c+1)*32 + khalf);
                pf[0] = src[0]; pf[1] = src[1]; pf[2] = src[2]; pf[3] = src[3];
            }
            __syncthreads();   // A chunk ready (single barrier per chunk; double-buffered)

            // two k16 steps over this 32-wide chunk
            const uint32_t aAddr = (buf ? aBase1 : aBase0);
#pragma unroll
            for (int ks = 0; ks < 2; ks++) {
                uint32_t aHf[4][4], aLf[4][4], bHf[2][4], bLf[2][4];
#pragma unroll
                for (int i = 0; i < 4; i++) {
                    ldsm_x4(aHf[i], aAddr + (uint32_t)(i*1280 + ks*32));
                    ldsm_x4(aLf[i], aAddr + (uint32_t)(10240 + i*1280 + ks*32));
                }
                const uint32_t cb = (uint32_t)(c*64 + ks*32);
#pragma unroll
                for (int jp = 0; jp < 2; jp++) {
                    ldsm_x4(bHf[jp], bLaneHi + (uint32_t)(jp*8448) + cb);
                    ldsm_x4(bLf[jp], bLaneLo + (uint32_t)(jp*8448) + cb);
                }
                // term 1: aHi * bHi
#pragma unroll
                for (int j = 0; j < 4; j++)
#pragma unroll
                    for (int i = 0; i < 4; i++)
                        mma16816(acc[i][j], aHf[i],
                                 bHf[j>>1][(j&1)*2], bHf[j>>1][(j&1)*2+1]);
                // term 2: aLo * bHi
#pragma unroll
                for (int j = 0; j < 4; j++)
#pragma unroll
                    for (int i = 0; i < 4; i++)
                        mma16816(acc[i][j], aLf[i],
                                 bHf[j>>1][(j&1)*2], bHf[j>>1][(j&1)*2+1]);
                // term 3: aHi * bLo
#pragma unroll
                for (int j = 0; j < 4; j++)
#pragma unroll
                    for (int i = 0; i < 4; i++)
                        mma16816(acc[i][j], aHf[i],
                                 bLf[j>>1][(j&1)*2], bLf[j>>1][(j&1)*2+1]);
            }
        }

        // ---- fused epilogue: bias + stats + 16-row max/min pool via shuffles ----
#pragma unroll
        for (int i = 0; i < 4; i++) {
            int q = mtile*8 + warp_m*4 + i;
#pragma unroll
            for (int j = 0; j < 4; j++) {
                float v0 = acc[i][j][0] + b2v[j][0];
                float v1 = acc[i][j][1] + b2v[j][1];
                float v2 = acc[i][j][2] + b2v[j][0];
                float v3 = acc[i][j][3] + b2v[j][1];
                st_s[j][0] += v0 + v2;
                st_q[j][0] += v0*v0 + v2*v2;
                st_s[j][1] += v1 + v3;
                st_q[j][1] += v1*v1 + v3*v3;
                float mx0 = fmaxf(v0, v2), mn0 = fminf(v0, v2);
                float mx1 = fmaxf(v1, v3), mn1 = fminf(v1, v3);
#pragma unroll
                for (int s = 4; s <= 16; s <<= 1) {
                    mx0 = fmaxf(mx0, __shfl_xor_sync(0xffffffffu, mx0, s));
                    mn0 = fminf(mn0, __shfl_xor_sync(0xffffffffu, mn0, s));
                    mx1 = fmaxf(mx1, __shfl_xor_sync(0xffffffffu, mx1, s));
                    mn1 = fminf(mn1, __shfl_xor_sync(0xffffffffu, mn1, s));
                }
                if (lane < 4) {
                    int col = nh*128 + warp_n*32 + j*8 + 2*lane;
                    g_hmax[(size_t)q*CO + col]     = mx0;
                    g_hmax[(size_t)q*CO + col + 1] = mx1;
                    g_hmin[(size_t)q*CO + col]     = mn0;
                    g_hmin[(size_t)q*CO + col + 1] = mn1;
                }
            }
        }
    }

    // flush BN2 stats (8 columns per thread, partial over this thread's rows)
#pragma unroll
    for (int j = 0; j < 4; j++) {
        atomicAdd(&g_sum2  [colb + j*8],     st_s[j][0]);
        atomicAdd(&g_sumsq2[colb + j*8],     st_q[j][0]);
        atomicAdd(&g_sum2  [colb + j*8 + 1], st_s[j][1]);
        atomicAdd(&g_sumsq2[colb + j*8 + 1], st_q[j][1]);
    }
}

// ---------------- final: out = relu(bn2(max-or-min)) ----------------
__global__ __launch_bounds__(256)
void final_out_kernel(float* __restrict__ out)
{
    int t = blockIdx.x * 256 + threadIdx.x;       // 0 .. QTOT*64
    int row = t >> 6, cg = t & 63;
    int c = cg * 4;
    float4 mx = *(const float4*)(g_hmax + (size_t)row*CO + c);
    float4 mn = *(const float4*)(g_hmin + (size_t)row*CO + c);
    float s0 = g_sc2[c+0], s1 = g_sc2[c+1], s2 = g_sc2[c+2], s3 = g_sc2[c+3];
    float h0 = g_sh2[c+0], h1 = g_sh2[c+1], h2 = g_sh2[c+2], h3 = g_sh2[c+3];
    float4 r;
    r.x = fmaxf(0.f, fmaf(s0 >= 0.f ? mx.x : mn.x, s0, h0));
    r.y = fmaxf(0.f, fmaf(s1 >= 0.f ? mx.y : mn.y, s1, h1));
    r.z = fmaxf(0.f, fmaf(s2 >= 0.f ? mx.z : mn.z, s2, h2));
    r.w = fmaxf(0.f, fmaf(s3 >= 0.f ? mx.w : mn.w, s3, h3));
    *(float4*)(out + NEWPOS_ELEMS + (size_t)row*CO + c) = r;
}

// ---------------- launch ----------------
extern "C" void kernel_launch(void* const* d_in, const int* in_sizes, int n_in,
                              void* d_out, int out_size)
{
    const float* pos    = (const float*)d_in[0];
    const float* points = (const float*)d_in[1];
    const int*   idx    = (const int*)  d_in[2];
    const float* W1     = (const float*)d_in[3];
    const float* b1     = (const float*)d_in[4];
    const float* g1     = (const float*)d_in[5];
    const float* beta1  = (const float*)d_in[6];
    const float* W2     = (const float*)d_in[7];
    const float* b2     = (const float*)d_in[8];
    const float* g2     = (const float*)d_in[9];
    const float* beta2  = (const float*)d_in[10];
    float* out = (float*)d_out;

    float *pP, *pSum1, *pSq1, *pSum2, *pSq2, *pSc1, *pSh1, *pSc2, *pSh2;
    cudaGetSymbolAddress((void**)&pP,   g_P);
    cudaGetSymbolAddress((void**)&pSum1,g_sum1);
    cudaGetSymbolAddress((void**)&pSq1, g_sumsq1);
    cudaGetSymbolAddress((void**)&pSum2,g_sum2);
    cudaGetSymbolAddress((void**)&pSq2, g_sumsq2);
    cudaGetSymbolAddress((void**)&pSc1, g_sc1);
    cudaGetSymbolAddress((void**)&pSh1, g_sh1);
    cudaGetSymbolAddress((void**)&pSc2, g_sc2);
    cudaGetSymbolAddress((void**)&pSh2, g_sh2);

    cudaFuncSetAttribute(gemm2_mma_kernel,
                         cudaFuncAttributeMaxDynamicSharedMemorySize, SMEM_G2);

    zero_stats_kernel<<<1, 256>>>();
    knn_kernel<<<QTOT/128, 128>>>(pos, idx, out);
    split_w2_kernel<<<CO*CO/256, 256>>>(W2);

    gemm_p_kernel<<<dim3((BB*NN)/128, CO/128), 256>>>(points, CC, W1, CI1, 3, pP, CC);

    assemble_h1_kernel<<<ROWS/64, 256>>>(pos, idx, W1, b1);
    finalize_bn_kernel<<<1, 256>>>(pSum1, pSq1, g1, beta1, pSc1, pSh1);

    gemm2_mma_kernel<<<148, 256, SMEM_G2>>>(b2);

    finalize_bn_kernel<<<1, 256>>>(pSum2, pSq2, g2, beta2, pSc2, pSh2);
    final_out_kernel<<<(QTOT*64)/256, 256>>>(out);
}

// round 11
// speedup vs baseline: 1.7679x; 1.0555x over previous
#include <cuda_runtime.h>
#include <cuda_bf16.h>
#include <float.h>
#include <cstdint>

// Problem constants
#define BB   8
#define NN   8192
#define MM   4096
#define CC   128
#define KNN  16
#define CO   256          // output channels of both layers
#define CI1  131          // 3 + 128
#define ROWS (BB*MM*KNN)  // 524288
#define QTOT (BB*MM)      // 32768
#define NEWPOS_ELEMS (QTOT*3)   // 98304
#define NTILE (ROWS/128)        // 4096 M-tiles
#define NWORK (2*NTILE)         // 8192 work items (M-tile x N-half)

// ---------------- static scratch (allocation-free rule) ----------------
__device__ float g_P [ (size_t)BB*NN*CO ];       // 64 MB   points @ W1p^T
__device__ float g_h1[ (size_t)ROWS*CO ];        // 512 MB  layer1 pre-activations
__device__ float g_hmax[ (size_t)QTOT*CO ];      // 32 MB   max_k h2 (pre-BN2, +b2)
__device__ float g_hmin[ (size_t)QTOT*CO ];      // 32 MB   min_k h2
__device__ int   g_knn[ ROWS ];                  // 2 MB
__device__ __nv_bfloat16 g_Bhi[CO*CO];           // W2 split hi
__device__ __nv_bfloat16 g_Blo[CO*CO];           // W2 split lo
__device__ float g_sum1[CO], g_sumsq1[CO], g_sum2[CO], g_sumsq2[CO];

// ---------------- kNN (one thread per query, register top-16) + stat zeroing ----
__global__ __launch_bounds__(128)
void knn_kernel(const float* __restrict__ pos, const int* __restrict__ idx,
                float* __restrict__ out_newpos)
{
    // fused: zero BN stats (block 0) — runs every graph replay before assemble/gemm2
    if (blockIdx.x == 0) {
        int tt = threadIdx.x;
        g_sum1[tt] = 0.f;  g_sum1[tt+128] = 0.f;
        g_sumsq1[tt] = 0.f; g_sumsq1[tt+128] = 0.f;
        g_sum2[tt] = 0.f;  g_sum2[tt+128] = 0.f;
        g_sumsq2[tt] = 0.f; g_sumsq2[tt+128] = 0.f;
    }

    __shared__ float4 sp[2048];
    const int q = blockIdx.x * 128 + threadIdx.x;
    const int b = q >> 12;
    const float* pb = pos + (size_t)b * NN * 3;

    const int nq = idx[q];
    const float qx = pb[nq*3+0], qy = pb[nq*3+1], qz = pb[nq*3+2];
    out_newpos[q*3+0] = qx; out_newpos[q*3+1] = qy; out_newpos[q*3+2] = qz;
    const float qn = qx*qx + qy*qy + qz*qz;

    float dist[KNN]; int ind[KNN];
#pragma unroll
    for (int j = 0; j < KNN; j++) { dist[j] = FLT_MAX; ind[j] = 0x7fffffff; }
    float wd = FLT_MAX; int wi = 0x7fffffff, wj = 0;

    for (int c0 = 0; c0 < NN; c0 += 2048) {
        __syncthreads();
        for (int i = threadIdx.x; i < 2048; i += 128) {
            float x = pb[(c0+i)*3+0], y = pb[(c0+i)*3+1], z = pb[(c0+i)*3+2];
            sp[i] = make_float4(x, y, z, x*x + y*y + z*z);
        }
        __syncthreads();
#pragma unroll 4
        for (int i = 0; i < 2048; i++) {
            float4 p = sp[i];
            float qp = qx*p.x + qy*p.y + qz*p.z;
            float d  = qn - 2.0f*qp + p.w;
            if (d < wd) {
                int nidx = c0 + i;
#pragma unroll
                for (int j = 0; j < KNN; j++) if (j == wj) { dist[j] = d; ind[j] = nidx; }
                wd = dist[0]; wi = ind[0]; wj = 0;
#pragma unroll
                for (int j = 1; j < KNN; j++) {
                    if (dist[j] > wd || (dist[j] == wd && ind[j] > wi)) {
                        wd = dist[j]; wi = ind[j]; wj = j;
                    }
                }
            }
        }
    }
#pragma unroll
    for (int j = 0; j < KNN; j++) g_knn[q*KNN + j] = ind[j];
}

// ---------------- tiled SGEMM for P = points @ W1p^T  (+ fused W2 split) ------
__global__ __launch_bounds__(256, 2)
void gemm_p_kernel(const float* __restrict__ A, int lda,
                   const float* __restrict__ Bw, int ldb, int boff,
                   float* __restrict__ C, int Kdim,
                   const float* __restrict__ W2)
{
    // fused: split W2 into bf16 hi/lo (256 blocks x 256 threads covers 65536)
    if (blockIdx.y == 0 && blockIdx.x < 256) {
        int i = blockIdx.x * 256 + threadIdx.x;
        float v = W2[i];
        __nv_bfloat16 h = __float2bfloat16(v);
        g_Bhi[i] = h;
        g_Blo[i] = __float2bfloat16(v - __bfloat162float(h));
    }

    const int BM = 128, BN = 128, BK = 16;
    __shared__ float As[BK][BM];
    __shared__ float Bs[BK][BN];

    const int t  = threadIdx.x;
    const int tx = t & 15, ty = t >> 4;
    const int rowBase = blockIdx.x * BM;
    const int colBase = blockIdx.y * BN;

    float acc[8][8];
#pragma unroll
    for (int i = 0; i < 8; i++)
#pragma unroll
        for (int j = 0; j < 8; j++) acc[i][j] = 0.f;

    for (int k0 = 0; k0 < Kdim; k0 += BK) {
#pragma unroll
        for (int l = 0; l < 2; l++) {
            int fid = t + l*256;
            int row = fid >> 2, c4 = (fid & 3) * 4;
            float4 v = *(const float4*)(A + (size_t)(rowBase + row)*lda + k0 + c4);
            As[c4+0][row] = v.x; As[c4+1][row] = v.y;
            As[c4+2][row] = v.z; As[c4+3][row] = v.w;
        }
#pragma unroll
        for (int l = 0; l < 8; l++) {
            int e = t + l*256;
            int c = e & 15, o = e >> 4;
            Bs[c][o] = Bw[(size_t)(colBase + o)*ldb + boff + k0 + c];
        }
        __syncthreads();
#pragma unroll
        for (int kk = 0; kk < BK; kk++) {
            float4 a0 = *(const float4*)&As[kk][ty*8];
            float4 a1 = *(const float4*)&As[kk][ty*8+4];
            float4 b0 = *(const float4*)&Bs[kk][tx*8];
            float4 b1 = *(const float4*)&Bs[kk][tx*8+4];
            float aR[8] = {a0.x,a0.y,a0.z,a0.w,a1.x,a1.y,a1.z,a1.w};
            float bR[8] = {b0.x,b0.y,b0.z,b0.w,b1.x,b1.y,b1.z,b1.w};
#pragma unroll
            for (int i = 0; i < 8; i++)
#pragma unroll
                for (int j = 0; j < 8; j++)
                    acc[i][j] = fmaf(aR[i], bR[j], acc[i][j]);
        }
        __syncthreads();
    }
#pragma unroll
    for (int i = 0; i < 8; i++) {
        int row = rowBase + ty*8 + i;
        float* cp = C + (size_t)row*CO + colBase + tx*8;
        *(float4*)cp       = make_float4(acc[i][0], acc[i][1], acc[i][2], acc[i][3]);
        *(float4*)(cp + 4) = make_float4(acc[i][4], acc[i][5], acc[i][6], acc[i][7]);
    }
}

// ---------------- assemble h1 = P[knn] + W1r*rel + b1  (+ stats) ----------------
__global__ __launch_bounds__(256)
void assemble_h1_kernel(const float* __restrict__ pos, const int* __restrict__ idx,
                        const float* __restrict__ W1, const float* __restrict__ b1)
{
    const int RPB = 64;
    __shared__ int   s_pb[RPB];
    __shared__ float s_r[RPB][3];
    const int base = blockIdx.x * RPB;
    const int t = threadIdx.x;
    if (t < RPB) {
        int r  = base + t;
        int b  = r >> 16;
        int m  = (r >> 4) & 4095;
        int nn = g_knn[r];
        const float* pb = pos + (size_t)b * NN * 3;
        int nq = idx[b*MM + m];
        s_r[t][0] = pb[nn*3+0] - pb[nq*3+0];
        s_r[t][1] = pb[nn*3+1] - pb[nq*3+1];
        s_r[t][2] = pb[nn*3+2] - pb[nq*3+2];
        s_pb[t]   = (b*NN + nn) * CO;
    }
    __syncthreads();
    const int o = t;
    const float w0 = W1[o*CI1+0], w1 = W1[o*CI1+1], w2 = W1[o*CI1+2], bb = b1[o];
    float ls = 0.f, lss = 0.f;
#pragma unroll 4
    for (int rr = 0; rr < RPB; rr++) {
        float v = g_P[(size_t)s_pb[rr] + o];
        v = v + bb + w0*s_r[rr][0] + w1*s_r[rr][1] + w2*s_r[rr][2];
        g_h1[(size_t)(base + rr)*CO + o] = v;
        ls += v; lss += v*v;
    }
    atomicAdd(&g_sum1[o], ls);
    atomicAdd(&g_sumsq1[o], lss);
}

// ================= GEMM2 via mma.sync bf16 (3-term split), 512 threads ========
// SMEM map (dynamic):
//   [0,1024)        s_sc (BN1 scale)   [1024,2048) s_sh   [2048,3072) s_b2
//   [3072,+67584)   B hi: 128 rows x 264 bf16 (pad 8) = 528 B/row
//   [70656,+67584)  B lo
//   [138240,+40960) A double-buffered: buf{0,1} x {hi,lo}, each 128 rows x 80 B
#define SM2_SC   0
#define SM2_SH   1024
#define SM2_B2   2048
#define SM2_BHI  3072
#define SM2_BLO  (SM2_BHI + 67584)
#define SM2_A    (SM2_BLO + 67584)     // 138240
#define SM2_ABUF 20480                 // one buffer = hi(10240) + lo(10240)
#define SMEM_G2  (SM2_A + 2*SM2_ABUF)  // 179200 bytes

__device__ __forceinline__ void mma16816(float* c, const uint32_t* a,
                                         uint32_t b0, uint32_t b1) {
    asm volatile(
        "mma.sync.aligned.m16n8k16.row.col.f32.bf16.bf16.f32 "
        "{%0,%1,%2,%3}, {%4,%5,%6,%7}, {%8,%9}, {%0,%1,%2,%3};\n"
        : "+f"(c[0]), "+f"(c[1]), "+f"(c[2]), "+f"(c[3])
        : "r"(a[0]), "r"(a[1]), "r"(a[2]), "r"(a[3]), "r"(b0), "r"(b1));
}
__device__ __forceinline__ void ldsm_x4(uint32_t* r, uint32_t addr) {
    asm volatile("ldmatrix.sync.aligned.m8n8.x4.shared.b16 {%0,%1,%2,%3}, [%4];"
                 : "=r"(r[0]), "=r"(r[1]), "=r"(r[2]), "=r"(r[3]) : "r"(addr));
}
__device__ __forceinline__ uint32_t cvt_bf2(float lo, float hi) {
    __nv_bfloat162 h = __float22bfloat162_rn(make_float2(lo, hi));
    return *reinterpret_cast<uint32_t*>(&h);
}

__global__ __launch_bounds__(512, 1)
void gemm2_mma_kernel(const float* __restrict__ b2,
                      const float* __restrict__ g1, const float* __restrict__ beta1)
{
    extern __shared__ char smx[];
    float* s_sc = (float*)(smx + SM2_SC);
    float* s_sh = (float*)(smx + SM2_SH);
    float* s_b2 = (float*)(smx + SM2_B2);
    char*  sBhi = smx + SM2_BHI;
    char*  sBlo = smx + SM2_BLO;

    const int t    = threadIdx.x;
    const int lane = t & 31, wid = t >> 5;
    const int warp_m = wid & 3;         // 0..3  -> 32-row quarter
    const int warp_n = wid >> 2;        // 0..3  -> 32-col slice
    const int nh   = blockIdx.x & 1;    // N-half (grid stride even -> fixed)

    const uint32_t smemBase = (uint32_t)__cvta_generic_to_shared(smx);

    // fused BN1 finalize (each CTA computes its own copy)
    if (t < 256) {
        const float inv = 1.0f / (float)ROWS;
        float mean = g_sum1[t] * inv;
        float var  = g_sumsq1[t] * inv - mean*mean;
        float s = g1[t] * rsqrtf(var + 1e-5f);
        s_sc[t] = s;
        s_sh[t] = fmaf(-mean, s, beta1[t]);
        s_b2[t] = b2[t];
    }

    // resident B half (hi/lo): 128 rows x 256 ch, padded rows of 528 B
#pragma unroll
    for (int l = 0; l < 8; l++) {
        int e = t + l*512;
        int n = e >> 5, k8 = e & 31;
        size_t gsrc = ((size_t)(nh*128 + n))*CO + k8*8;
        *(uint4*)(sBhi + n*528 + k8*16) = *(const uint4*)(g_Bhi + gsrc);
        *(uint4*)(sBlo + n*528 + k8*16) = *(const uint4*)(g_Blo + gsrc);
    }

    // per-thread stats registers (cols fixed for this thread)
    float st_s[4][2], st_q[4][2];
    const int colb = nh*128 + warp_n*32 + 2*(lane & 3);
#pragma unroll
    for (int j = 0; j < 4; j++) {
        st_s[j][0] = st_s[j][1] = 0.f;
        st_q[j][0] = st_q[j][1] = 0.f;
    }

    // ldmatrix lane-address bases
    // A x4 (m16k16): lanes 0-7:(m0-7,k0) 8-15:(m8-15,k0) 16-23:(m0-7,k8) 24-31:(m8-15,k8)
    const int aM = warp_m*32 + (lane & 7) + ((lane >> 3) & 1)*8;
    const uint32_t aLane = (uint32_t)(aM*80 + (lane >> 4)*16);
    const uint32_t aBase0 = smemBase + SM2_A + aLane;              // buf0 hi
    const uint32_t aBase1 = smemBase + SM2_A + SM2_ABUF + aLane;   // buf1 hi
    // B x4 (two n8 x k16): lanes 0-7:(n0-7,k0) 8-15:(n0-7,k8) 16-23:(n8-15,k0) 24-31:(n8-15,k8)
    const int bN = warp_n*32 + (lane & 7) + (lane >> 4)*8;
    const uint32_t bKoff = ((lane >> 3) & 1)*16;
    const uint32_t bLaneHi = smemBase + SM2_BHI + bN*528 + bKoff;
    const uint32_t bLaneLo = smemBase + SM2_BLO + bN*528 + bKoff;

    const int qrow = t >> 2;            // loader row 0..127
    const int kq   = (t & 3) * 8;       // loader 8-channel offset within 32-chunk

    __syncthreads();   // params + B resident visible before first use

    for (int wi = blockIdx.x; wi < NWORK; wi += gridDim.x) {
        const int mtile = wi >> 1;
        const size_t rowBase = (size_t)mtile * 128;

        float acc[2][4][4];
#pragma unroll
        for (int i = 0; i < 2; i++)
#pragma unroll
            for (int j = 0; j < 4; j++)
#pragma unroll
                for (int d = 0; d < 4; d++) acc[i][j][d] = 0.f;

        // prefetch chunk 0 (8 channels per thread)
        float4 pf0, pf1;
        {
            const float4* src = (const float4*)(g_h1 + (rowBase + qrow)*CO + kq);
            pf0 = src[0]; pf1 = src[1];
        }

        for (int c = 0; c < 8; c++) {
            const int buf = c & 1;
            // store prefetched chunk -> A buf with BN1+ReLU + hi/lo split
            {
                char* aH = smx + SM2_A + buf*SM2_ABUF + qrow*80 + kq*2;
                const int cb = c*32 + kq;
                float x[8] = {pf0.x, pf0.y, pf0.z, pf0.w, pf1.x, pf1.y, pf1.z, pf1.w};
#pragma unroll
                for (int v = 0; v < 8; v++)
                    x[v] = fmaxf(0.f, fmaf(x[v], s_sc[cb+v], s_sh[cb+v]));
                uint32_t uh[4], ul[4];
#pragma unroll
                for (int p = 0; p < 4; p++) uh[p] = cvt_bf2(x[2*p], x[2*p+1]);
#pragma unroll
                for (int p = 0; p < 4; p++) {
                    float l0 = x[2*p]   - __uint_as_float(uh[p] << 16);
                    float l1 = x[2*p+1] - __uint_as_float(uh[p] & 0xffff0000u);
                    ul[p] = cvt_bf2(l0, l1);
                }
                *(uint4*)(aH)         = make_uint4(uh[0], uh[1], uh[2], uh[3]);
                *(uint4*)(aH + 10240) = make_uint4(ul[0], ul[1], ul[2], ul[3]);
            }
            // prefetch next chunk (LDG latency overlaps mma below)
            if (c < 7) {
                const float4* src = (const float4*)(g_h1 + (rowBase + qrow)*CO
                                                    + (c+1)*32 + kq);
                pf0 = src[0]; pf1 = src[1];
            }
            __syncthreads();   // A chunk ready (single barrier; double-buffered)

            const uint32_t aAddr = (buf ? aBase1 : aBase0);
#pragma unroll
            for (int ks = 0; ks < 2; ks++) {
                uint32_t aHf[2][4], aLf[2][4], bHf[2][4], bLf[2][4];
#pragma unroll
                for (int i = 0; i < 2; i++) {
                    ldsm_x4(aHf[i], aAddr + (uint32_t)(i*1280 + ks*32));
                    ldsm_x4(aLf[i], aAddr + (uint32_t)(10240 + i*1280 + ks*32));
                }
                const uint32_t cb = (uint32_t)(c*64 + ks*32);
#pragma unroll
                for (int jp = 0; jp < 2; jp++) {
                    ldsm_x4(bHf[jp], bLaneHi + (uint32_t)(jp*8448) + cb);
                    ldsm_x4(bLf[jp], bLaneLo + (uint32_t)(jp*8448) + cb);
                }
                // term 1: aHi * bHi
#pragma unroll
                for (int j = 0; j < 4; j++)
#pragma unroll
                    for (int i = 0; i < 2; i++)
                        mma16816(acc[i][j], aHf[i],
                                 bHf[j>>1][(j&1)*2], bHf[j>>1][(j&1)*2+1]);
                // term 2: aLo * bHi
#pragma unroll
                for (int j = 0; j < 4; j++)
#pragma unroll
                    for (int i = 0; i < 2; i++)
                        mma16816(acc[i][j], aLf[i],
                                 bHf[j>>1][(j&1)*2], bHf[j>>1][(j&1)*2+1]);
                // term 3: aHi * bLo
#pragma unroll
                for (int j = 0; j < 4; j++)
#pragma unroll
                    for (int i = 0; i < 2; i++)
                        mma16816(acc[i][j], aHf[i],
                                 bLf[j>>1][(j&1)*2], bLf[j>>1][(j&1)*2+1]);
            }
        }

        // ---- fused epilogue: bias + stats + 16-row max/min pool via shuffles ----
#pragma unroll
        for (int i = 0; i < 2; i++) {
            int q = mtile*8 + warp_m*2 + i;
#pragma unroll
            for (int j = 0; j < 4; j++) {
                float bb0 = s_b2[nh*128 + warp_n*32 + j*8 + 2*(lane & 3)];
                float bb1 = s_b2[nh*128 + warp_n*32 + j*8 + 2*(lane & 3) + 1];
                float v0 = acc[i][j][0] + bb0;
                float v1 = acc[i][j][1] + bb1;
                float v2 = acc[i][j][2] + bb0;
                float v3 = acc[i][j][3] + bb1;
                st_s[j][0] += v0 + v2;
                st_q[j][0] += v0*v0 + v2*v2;
                st_s[j][1] += v1 + v3;
                st_q[j][1] += v1*v1 + v3*v3;
                float mx0 = fmaxf(v0, v2), mn0 = fminf(v0, v2);
                float mx1 = fmaxf(v1, v3), mn1 = fminf(v1, v3);
#pragma unroll
                for (int s = 4; s <= 16; s <<= 1) {
                    mx0 = fmaxf(mx0, __shfl_xor_sync(0xffffffffu, mx0, s));
                    mn0 = fminf(mn0, __shfl_xor_sync(0xffffffffu, mn0, s));
                    mx1 = fmaxf(mx1, __shfl_xor_sync(0xffffffffu, mx1, s));
                    mn1 = fminf(mn1, __shfl_xor_sync(0xffffffffu, mn1, s));
                }
                if (lane < 4) {
                    int col = nh*128 + warp_n*32 + j*8 + 2*lane;
                    g_hmax[(size_t)q*CO + col]     = mx0;
                    g_hmax[(size_t)q*CO + col + 1] = mx1;
                    g_hmin[(size_t)q*CO + col]     = mn0;
                    g_hmin[(size_t)q*CO + col + 1] = mn1;
                }
            }
        }
    }

    // flush BN2 stats (8 columns per thread, partial over this thread's rows)
#pragma unroll
    for (int j = 0; j < 4; j++) {
        atomicAdd(&g_sum2  [colb + j*8],     st_s[j][0]);
        atomicAdd(&g_sumsq2[colb + j*8],     st_q[j][0]);
        atomicAdd(&g_sum2  [colb + j*8 + 1], st_s[j][1]);
        atomicAdd(&g_sumsq2[colb + j*8 + 1], st_q[j][1]);
    }
}

// ---------------- final: out = relu(bn2(max-or-min))  (+ fused BN2 finalize) ----
__global__ __launch_bounds__(256)
void final_out_kernel(float* __restrict__ out,
                      const float* __restrict__ g2, const float* __restrict__ beta2)
{
    __shared__ float s_sc2[CO], s_sh2[CO];
    {
        int o = threadIdx.x;
        const float inv = 1.0f / (float)ROWS;
        float mean = g_sum2[o] * inv;
        float var  = g_sumsq2[o] * inv - mean*mean;
        float s = g2[o] * rsqrtf(var + 1e-5f);
        s_sc2[o] = s;
        s_sh2[o] = fmaf(-mean, s, beta2[o]);
    }
    __syncthreads();

    int t = blockIdx.x * 256 + threadIdx.x;       // 0 .. QTOT*64
    int row = t >> 6, cg = t & 63;
    int c = cg * 4;
    float4 mx = *(const float4*)(g_hmax + (size_t)row*CO + c);
    float4 mn = *(const float4*)(g_hmin + (size_t)row*CO + c);
    float s0 = s_sc2[c+0], s1 = s_sc2[c+1], s2 = s_sc2[c+2], s3 = s_sc2[c+3];
    float h0 = s_sh2[c+0], h1 = s_sh2[c+1], h2 = s_sh2[c+2], h3 = s_sh2[c+3];
    float4 r;
    r.x = fmaxf(0.f, fmaf(s0 >= 0.f ? mx.x : mn.x, s0, h0));
    r.y = fmaxf(0.f, fmaf(s1 >= 0.f ? mx.y : mn.y, s1, h1));
    r.z = fmaxf(0.f, fmaf(s2 >= 0.f ? mx.z : mn.z, s2, h2));
    r.w = fmaxf(0.f, fmaf(s3 >= 0.f ? mx.w : mn.w, s3, h3));
    *(float4*)(out + NEWPOS_ELEMS + (size_t)row*CO + c) = r;
}

// ---------------- launch ----------------
extern "C" void kernel_launch(void* const* d_in, const int* in_sizes, int n_in,
                              void* d_out, int out_size)
{
    const float* pos    = (const float*)d_in[0];
    const float* points = (const float*)d_in[1];
    const int*   idx    = (const int*)  d_in[2];
    const float* W1     = (const float*)d_in[3];
    const float* b1     = (const float*)d_in[4];
    const float* g1     = (const float*)d_in[5];
    const float* beta1  = (const float*)d_in[6];
    const float* W2     = (const float*)d_in[7];
    const float* b2     = (const float*)d_in[8];
    const float* g2     = (const float*)d_in[9];
    const float* beta2  = (const float*)d_in[10];
    float* out = (float*)d_out;

    float *pP;
    cudaGetSymbolAddress((void**)&pP, g_P);

    cudaFuncSetAttribute(gemm2_mma_kernel,
                         cudaFuncAttributeMaxDynamicSharedMemorySize, SMEM_G2);

    // launch 0: kNN (+ zero stats)
    knn_kernel<<<QTOT/128, 128>>>(pos, idx, out);
    // launch 1: P = points @ W1p^T (+ W2 bf16 split)
    gemm_p_kernel<<<dim3((BB*NN)/128, CO/128), 256>>>(points, CC, W1, CI1, 3, pP, CC, W2);
    // launch 2: h1 assembly + BN1 stats
    assemble_h1_kernel<<<ROWS/64, 256>>>(pos, idx, W1, b1);
    // launch 3: GEMM2 (tensor cores) + BN2 stats + pooled epilogue   <- ncu target
    gemm2_mma_kernel<<<148, 512, SMEM_G2>>>(b2, g1, beta1);
    // launch 4: BN2 finalize + output
    final_out_kernel<<<(QTOT*64)/256, 256>>>(out, g2, beta2);
}

// round 12
// speedup vs baseline: 2.4664x; 1.3951x over previous
#include <cuda_runtime.h>
#include <cuda_bf16.h>
#include <float.h>
#include <cstdint>

// Problem constants
#define BB   8
#define NN   8192
#define MM   4096
#define CC   128
#define KNN  16
#define CO   256          // output channels of both layers
#define CI1  131          // 3 + 128
#define ROWS (BB*MM*KNN)  // 524288
#define QTOT (BB*MM)      // 32768
#define NEWPOS_ELEMS (QTOT*3)   // 98304
#define NTILE (ROWS/128)        // 4096 M-tiles
#define NWORK (2*NTILE)         // 8192 work items (M-tile x N-half)

// ---------------- static scratch (allocation-free rule) ----------------
__device__ float g_P [ (size_t)BB*NN*CO ];       // 64 MB   points @ W1p^T
__device__ float g_h1[ (size_t)ROWS*CO ];        // 512 MB  layer1 pre-activations
__device__ float g_hmax[ (size_t)QTOT*CO ];      // 32 MB   max_k h2 (pre-BN2, +b2)
__device__ float g_hmin[ (size_t)QTOT*CO ];      // 32 MB   min_k h2
__device__ int   g_knn[ ROWS ];                  // 2 MB
__device__ __nv_bfloat16 g_Bhi[CO*CO];           // W2 split hi
__device__ __nv_bfloat16 g_Blo[CO*CO];           // W2 split lo
__device__ float g_sum1[CO], g_sumsq1[CO], g_sum2[CO], g_sumsq2[CO];

// ---------------- kNN: 256 thr/block (128 blocks = 1 wave), sorted-shift top-16
__global__ __launch_bounds__(256)
void knn_kernel(const float* __restrict__ pos, const int* __restrict__ idx,
                float* __restrict__ out_newpos)
{
    // fused: zero BN stats (block 0) — runs every graph replay
    if (blockIdx.x == 0 && threadIdx.x < CO) {
        int tt = threadIdx.x;
        g_sum1[tt] = 0.f;  g_sumsq1[tt] = 0.f;
        g_sum2[tt] = 0.f;  g_sumsq2[tt] = 0.f;
    }

    __shared__ float4 sp[2048];
    const int q = blockIdx.x * 256 + threadIdx.x;
    const int b = q >> 12;
    const float* pb = pos + (size_t)b * NN * 3;

    const int nq = idx[q];
    const float qx = pb[nq*3+0], qy = pb[nq*3+1], qz = pb[nq*3+2];
    out_newpos[q*3+0] = qx; out_newpos[q*3+1] = qy; out_newpos[q*3+2] = qz;
    const float qn = qx*qx + qy*qy + qz*qz;

    // descending-sorted by distance: dist[0] = worst of the kept 16
    float dist[KNN]; int ind[KNN];
#pragma unroll
    for (int j = 0; j < KNN; j++) { dist[j] = FLT_MAX; ind[j] = 0x7fffffff; }

    for (int c0 = 0; c0 < NN; c0 += 2048) {
        __syncthreads();
        for (int i = threadIdx.x; i < 2048; i += 256) {
            float x = pb[(c0+i)*3+0], y = pb[(c0+i)*3+1], z = pb[(c0+i)*3+2];
            sp[i] = make_float4(x, y, z, x*x + y*y + z*z);
        }
        __syncthreads();
#pragma unroll 4
        for (int i = 0; i < 2048; i++) {
            float4 p = sp[i];
            float qp = qx*p.x + qy*p.y + qz*p.z;
            float d  = qn - 2.0f*qp + p.w;               // same expansion as reference
            if (d < dist[0]) {
                const int nidx = c0 + i;
                // predicated sorted shift-insert (worst drops off at slot 0)
                bool prev = true;
#pragma unroll
                for (int j = 0; j < KNN-1; j++) {
                    bool nxt = d < dist[j+1];
                    float dj = nxt ? dist[j+1] : (prev ? d    : dist[j]);
                    int   ij = nxt ? ind[j+1]  : (prev ? nidx : ind[j]);
                    dist[j] = dj; ind[j] = ij;
                    prev = nxt;
                }
                if (prev) { dist[KNN-1] = d; ind[KNN-1] = nidx; }
            }
        }
    }
#pragma unroll
    for (int j = 0; j < KNN; j++) g_knn[q*KNN + j] = ind[j];
}

// ---------------- tiled SGEMM for P = points @ W1p^T  (+ fused W2 split) ------
__global__ __launch_bounds__(256, 2)
void gemm_p_kernel(const float* __restrict__ A, int lda,
                   const float* __restrict__ Bw, int ldb, int boff,
                   float* __restrict__ C, int Kdim,
                   const float* __restrict__ W2)
{
    // fused: split W2 into bf16 hi/lo (256 blocks x 256 threads covers 65536)
    if (blockIdx.y == 0 && blockIdx.x < 256) {
        int i = blockIdx.x * 256 + threadIdx.x;
        float v = W2[i];
        __nv_bfloat16 h = __float2bfloat16(v);
        g_Bhi[i] = h;
        g_Blo[i] = __float2bfloat16(v - __bfloat162float(h));
    }

    const int BM = 128, BN = 128, BK = 16;
    __shared__ float As[BK][BM];
    __shared__ float Bs[BK][BN];

    const int t  = threadIdx.x;
    const int tx = t & 15, ty = t >> 4;
    const int rowBase = blockIdx.x * BM;
    const int colBase = blockIdx.y * BN;

    float acc[8][8];
#pragma unroll
    for (int i = 0; i < 8; i++)
#pragma unroll
        for (int j = 0; j < 8; j++) acc[i][j] = 0.f;

    for (int k0 = 0; k0 < Kdim; k0 += BK) {
#pragma unroll
        for (int l = 0; l < 2; l++) {
            int fid = t + l*256;
            int row = fid >> 2, c4 = (fid & 3) * 4;
            float4 v = *(const float4*)(A + (size_t)(rowBase + row)*lda + k0 + c4);
            As[c4+0][row] = v.x; As[c4+1][row] = v.y;
            As[c4+2][row] = v.z; As[c4+3][row] = v.w;
        }
#pragma unroll
        for (int l = 0; l < 8; l++) {
            int e = t + l*256;
            int c = e & 15, o = e >> 4;
            Bs[c][o] = Bw[(size_t)(colBase + o)*ldb + boff + k0 + c];
        }
        __syncthreads();
#pragma unroll
        for (int kk = 0; kk < BK; kk++) {
            float4 a0 = *(const float4*)&As[kk][ty*8];
            float4 a1 = *(const float4*)&As[kk][ty*8+4];
            float4 b0 = *(const float4*)&Bs[kk][tx*8];
            float4 b1 = *(const float4*)&Bs[kk][tx*8+4];
            float aR[8] = {a0.x,a0.y,a0.z,a0.w,a1.x,a1.y,a1.z,a1.w};
            float bR[8] = {b0.x,b0.y,b0.z,b0.w,b1.x,b1.y,b1.z,b1.w};
#pragma unroll
            for (int i = 0; i < 8; i++)
#pragma unroll
                for (int j = 0; j < 8; j++)
                    acc[i][j] = fmaf(aR[i], bR[j], acc[i][j]);
        }
        __syncthreads();
    }
#pragma unroll
    for (int i = 0; i < 8; i++) {
        int row = rowBase + ty*8 + i;
        float* cp = C + (size_t)row*CO + colBase + tx*8;
        *(float4*)cp       = make_float4(acc[i][0], acc[i][1], acc[i][2], acc[i][3]);
        *(float4*)(cp + 4) = make_float4(acc[i][4], acc[i][5], acc[i][6], acc[i][7]);
    }
}

// ---------------- assemble h1 = P[knn] + W1r*rel + b1  (+ stats) ----------------
__global__ __launch_bounds__(256)
void assemble_h1_kernel(const float* __restrict__ pos, const int* __restrict__ idx,
                        const float* __restrict__ W1, const float* __restrict__ b1)
{
    const int RPB = 64;
    __shared__ int   s_pb[RPB];
    __shared__ float s_r[RPB][3];
    const int base = blockIdx.x * RPB;
    const int t = threadIdx.x;
    if (t < RPB) {
        int r  = base + t;
        int b  = r >> 16;
        int m  = (r >> 4) & 4095;
        int nn = g_knn[r];
        const float* pb = pos + (size_t)b * NN * 3;
        int nq = idx[b*MM + m];
        s_r[t][0] = pb[nn*3+0] - pb[nq*3+0];
        s_r[t][1] = pb[nn*3+1] - pb[nq*3+1];
        s_r[t][2] = pb[nn*3+2] - pb[nq*3+2];
        s_pb[t]   = (b*NN + nn) * CO;
    }
    __syncthreads();
    const int o = t;
    const float w0 = W1[o*CI1+0], w1 = W1[o*CI1+1], w2 = W1[o*CI1+2], bb = b1[o];
    float ls = 0.f, lss = 0.f;
#pragma unroll 4
    for (int rr = 0; rr < RPB; rr++) {
        float v = g_P[(size_t)s_pb[rr] + o];
        v = v + bb + w0*s_r[rr][0] + w1*s_r[rr][1] + w2*s_r[rr][2];
        g_h1[(size_t)(base + rr)*CO + o] = v;
        ls += v; lss += v*v;
    }
    atomicAdd(&g_sum1[o], ls);
    atomicAdd(&g_sumsq1[o], lss);
}

// ================= GEMM2 via mma.sync bf16 (3-term split), 512 threads ========
#define SM2_SC   0
#define SM2_SH   1024
#define SM2_B2   2048
#define SM2_BHI  3072
#define SM2_BLO  (SM2_BHI + 67584)
#define SM2_A    (SM2_BLO + 67584)     // 138240
#define SM2_ABUF 20480                 // one buffer = hi(10240) + lo(10240)
#define SMEM_G2  (SM2_A + 2*SM2_ABUF)  // 179200 bytes

__device__ __forceinline__ void mma16816(float* c, const uint32_t* a,
                                         uint32_t b0, uint32_t b1) {
    asm volatile(
        "mma.sync.aligned.m16n8k16.row.col.f32.bf16.bf16.f32 "
        "{%0,%1,%2,%3}, {%4,%5,%6,%7}, {%8,%9}, {%0,%1,%2,%3};\n"
        : "+f"(c[0]), "+f"(c[1]), "+f"(c[2]), "+f"(c[3])
        : "r"(a[0]), "r"(a[1]), "r"(a[2]), "r"(a[3]), "r"(b0), "r"(b1));
}
__device__ __forceinline__ void ldsm_x4(uint32_t* r, uint32_t addr) {
    asm volatile("ldmatrix.sync.aligned.m8n8.x4.shared.b16 {%0,%1,%2,%3}, [%4];"
                 : "=r"(r[0]), "=r"(r[1]), "=r"(r[2]), "=r"(r[3]) : "r"(addr));
}
__device__ __forceinline__ uint32_t cvt_bf2(float lo, float hi) {
    __nv_bfloat162 h = __float22bfloat162_rn(make_float2(lo, hi));
    return *reinterpret_cast<uint32_t*>(&h);
}

__global__ __launch_bounds__(512, 1)
void gemm2_mma_kernel(const float* __restrict__ b2,
                      const float* __restrict__ g1, const float* __restrict__ beta1)
{
    extern __shared__ char smx[];
    float* s_sc = (float*)(smx + SM2_SC);
    float* s_sh = (float*)(smx + SM2_SH);
    float* s_b2 = (float*)(smx + SM2_B2);
    char*  sBhi = smx + SM2_BHI;
    char*  sBlo = smx + SM2_BLO;

    const int t    = threadIdx.x;
    const int lane = t & 31, wid = t >> 5;
    const int warp_m = wid & 3;         // 0..3  -> 32-row quarter
    const int warp_n = wid >> 2;        // 0..3  -> 32-col slice
    const int nh   = blockIdx.x & 1;    // N-half (grid stride even -> fixed)

    const uint32_t smemBase = (uint32_t)__cvta_generic_to_shared(smx);

    // fused BN1 finalize (each CTA computes its own copy)
    if (t < 256) {
        const float inv = 1.0f / (float)ROWS;
        float mean = g_sum1[t] * inv;
        float var  = g_sumsq1[t] * inv - mean*mean;
        float s = g1[t] * rsqrtf(var + 1e-5f);
        s_sc[t] = s;
        s_sh[t] = fmaf(-mean, s, beta1[t]);
        s_b2[t] = b2[t];
    }

    // resident B half (hi/lo): 128 rows x 256 ch, padded rows of 528 B
#pragma unroll
    for (int l = 0; l < 8; l++) {
        int e = t + l*512;
        int n = e >> 5, k8 = e & 31;
        size_t gsrc = ((size_t)(nh*128 + n))*CO + k8*8;
        *(uint4*)(sBhi + n*528 + k8*16) = *(const uint4*)(g_Bhi + gsrc);
        *(uint4*)(sBlo + n*528 + k8*16) = *(const uint4*)(g_Blo + gsrc);
    }

    // per-thread stats registers (cols fixed for this thread)
    float st_s[4][2], st_q[4][2];
    const int colb = nh*128 + warp_n*32 + 2*(lane & 3);
#pragma unroll
    for (int j = 0; j < 4; j++) {
        st_s[j][0] = st_s[j][1] = 0.f;
        st_q[j][0] = st_q[j][1] = 0.f;
    }

    // ldmatrix lane-address bases
    const int aM = warp_m*32 + (lane & 7) + ((lane >> 3) & 1)*8;
    const uint32_t aLane = (uint32_t)(aM*80 + (lane >> 4)*16);
    const uint32_t aBase0 = smemBase + SM2_A + aLane;              // buf0 hi
    const uint32_t aBase1 = smemBase + SM2_A + SM2_ABUF + aLane;   // buf1 hi
    const int bN = warp_n*32 + (lane & 7) + (lane >> 4)*8;
    const uint32_t bKoff = ((lane >> 3) & 1)*16;
    const uint32_t bLaneHi = smemBase + SM2_BHI + bN*528 + bKoff;
    const uint32_t bLaneLo = smemBase + SM2_BLO + bN*528 + bKoff;

    const int qrow = t >> 2;            // loader row 0..127
    const int kq   = (t & 3) * 8;       // loader 8-channel offset within 32-chunk

    __syncthreads();   // params + B resident visible before first use

    for (int wi = blockIdx.x; wi < NWORK; wi += gridDim.x) {
        const int mtile = wi >> 1;
        const size_t rowBase = (size_t)mtile * 128;

        float acc[2][4][4];
#pragma unroll
        for (int i = 0; i < 2; i++)
#pragma unroll
            for (int j = 0; j < 4; j++)
#pragma unroll
                for (int d = 0; d < 4; d++) acc[i][j][d] = 0.f;

        // prefetch chunk 0 (8 channels per thread)
        float4 pf0, pf1;
        {
            const float4* src = (const float4*)(g_h1 + (rowBase + qrow)*CO + kq);
            pf0 = src[0]; pf1 = src[1];
        }

        for (int c = 0; c < 8; c++) {
            const int buf = c & 1;
            // store prefetched chunk -> A buf with BN1+ReLU + hi/lo split
            {
                char* aH = smx + SM2_A + buf*SM2_ABUF + qrow*80 + kq*2;
                const int cb = c*32 + kq;
                float x[8] = {pf0.x, pf0.y, pf0.z, pf0.w, pf1.x, pf1.y, pf1.z, pf1.w};
#pragma unroll
                for (int v = 0; v < 8; v++)
                    x[v] = fmaxf(0.f, fmaf(x[v], s_sc[cb+v], s_sh[cb+v]));
                uint32_t uh[4], ul[4];
#pragma unroll
                for (int p = 0; p < 4; p++) uh[p] = cvt_bf2(x[2*p], x[2*p+1]);
#pragma unroll
                for (int p = 0; p < 4; p++) {
                    float l0 = x[2*p]   - __uint_as_float(uh[p] << 16);
                    float l1 = x[2*p+1] - __uint_as_float(uh[p] & 0xffff0000u);
                    ul[p] = cvt_bf2(l0, l1);
                }
                *(uint4*)(aH)         = make_uint4(uh[0], uh[1], uh[2], uh[3]);
                *(uint4*)(aH + 10240) = make_uint4(ul[0], ul[1], ul[2], ul[3]);
            }
            // prefetch next chunk (LDG latency overlaps mma below)
            if (c < 7) {
                const float4* src = (const float4*)(g_h1 + (rowBase + qrow)*CO
                                                    + (c+1)*32 + kq);
                pf0 = src[0]; pf1 = src[1];
            }
            __syncthreads();   // A chunk ready (single barrier; double-buffered)

            const uint32_t aAddr = (buf ? aBase1 : aBase0);
#pragma unroll
            for (int ks = 0; ks < 2; ks++) {
                uint32_t aHf[2][4], aLf[2][4], bHf[2][4], bLf[2][4];
#pragma unroll
                for (int i = 0; i < 2; i++) {
                    ldsm_x4(aHf[i], aAddr + (uint32_t)(i*1280 + ks*32));
                    ldsm_x4(aLf[i], aAddr + (uint32_t)(10240 + i*1280 + ks*32));
                }
                const uint32_t cb = (uint32_t)(c*64 + ks*32);
#pragma unroll
                for (int jp = 0; jp < 2; jp++) {
                    ldsm_x4(bHf[jp], bLaneHi + (uint32_t)(jp*8448) + cb);
                    ldsm_x4(bLf[jp], bLaneLo + (uint32_t)(jp*8448) + cb);
                }
#pragma unroll
                for (int j = 0; j < 4; j++)
#pragma unroll
                    for (int i = 0; i < 2; i++)
                        mma16816(acc[i][j], aHf[i],
                                 bHf[j>>1][(j&1)*2], bHf[j>>1][(j&1)*2+1]);
#pragma unroll
                for (int j = 0; j < 4; j++)
#pragma unroll
                    for (int i = 0; i < 2; i++)
                        mma16816(acc[i][j], aLf[i],
                                 bHf[j>>1][(j&1)*2], bHf[j>>1][(j&1)*2+1]);
#pragma unroll
                for (int j = 0; j < 4; j++)
#pragma unroll
                    for (int i = 0; i < 2; i++)
                        mma16816(acc[i][j], aHf[i],
                                 bLf[j>>1][(j&1)*2], bLf[j>>1][(j&1)*2+1]);
            }
        }

        // ---- fused epilogue: bias + stats + 16-row max/min pool via shuffles ----
#pragma unroll
        for (int i = 0; i < 2; i++) {
            int q = mtile*8 + warp_m*2 + i;
#pragma unroll
            for (int j = 0; j < 4; j++) {
                float bb0 = s_b2[nh*128 + warp_n*32 + j*8 + 2*(lane & 3)];
                float bb1 = s_b2[nh*128 + warp_n*32 + j*8 + 2*(lane & 3) + 1];
                float v0 = acc[i][j][0] + bb0;
                float v1 = acc[i][j][1] + bb1;
                float v2 = acc[i][j][2] + bb0;
                float v3 = acc[i][j][3] + bb1;
                st_s[j][0] += v0 + v2;
                st_q[j][0] += v0*v0 + v2*v2;
                st_s[j][1] += v1 + v3;
                st_q[j][1] += v1*v1 + v3*v3;
                float mx0 = fmaxf(v0, v2), mn0 = fminf(v0, v2);
                float mx1 = fmaxf(v1, v3), mn1 = fminf(v1, v3);
#pragma unroll
                for (int s = 4; s <= 16; s <<= 1) {
                    mx0 = fmaxf(mx0, __shfl_xor_sync(0xffffffffu, mx0, s));
                    mn0 = fminf(mn0, __shfl_xor_sync(0xffffffffu, mn0, s));
                    mx1 = fmaxf(mx1, __shfl_xor_sync(0xffffffffu, mx1, s));
                    mn1 = fminf(mn1, __shfl_xor_sync(0xffffffffu, mn1, s));
                }
                if (lane < 4) {
                    int col = nh*128 + warp_n*32 + j*8 + 2*lane;
                    g_hmax[(size_t)q*CO + col]     = mx0;
                    g_hmax[(size_t)q*CO + col + 1] = mx1;
                    g_hmin[(size_t)q*CO + col]     = mn0;
                    g_hmin[(size_t)q*CO + col + 1] = mn1;
                }
            }
        }
    }

    // flush BN2 stats (8 columns per thread, partial over this thread's rows)
#pragma unroll
    for (int j = 0; j < 4; j++) {
        atomicAdd(&g_sum2  [colb + j*8],     st_s[j][0]);
        atomicAdd(&g_sumsq2[colb + j*8],     st_q[j][0]);
        atomicAdd(&g_sum2  [colb + j*8 + 1], st_s[j][1]);
        atomicAdd(&g_sumsq2[colb + j*8 + 1], st_q[j][1]);
    }
}

// ---------------- final: out = relu(bn2(max-or-min))  (+ fused BN2 finalize) ----
__global__ __launch_bounds__(256)
void final_out_kernel(float* __restrict__ out,
                      const float* __restrict__ g2, const float* __restrict__ beta2)
{
    __shared__ float s_sc2[CO], s_sh2[CO];
    {
        int o = threadIdx.x;
        const float inv = 1.0f / (float)ROWS;
        float mean = g_sum2[o] * inv;
        float var  = g_sumsq2[o] * inv - mean*mean;
        float s = g2[o] * rsqrtf(var + 1e-5f);
        s_sc2[o] = s;
        s_sh2[o] = fmaf(-mean, s, beta2[o]);
    }
    __syncthreads();

    int t = blockIdx.x * 256 + threadIdx.x;       // 0 .. QTOT*64
    int row = t >> 6, cg = t & 63;
    int c = cg * 4;
    float4 mx = *(const float4*)(g_hmax + (size_t)row*CO + c);
    float4 mn = *(const float4*)(g_hmin + (size_t)row*CO + c);
    float s0 = s_sc2[c+0], s1 = s_sc2[c+1], s2 = s_sc2[c+2], s3 = s_sc2[c+3];
    float h0 = s_sh2[c+0], h1 = s_sh2[c+1], h2 = s_sh2[c+2], h3 = s_sh2[c+3];
    float4 r;
    r.x = fmaxf(0.f, fmaf(s0 >= 0.f ? mx.x : mn.x, s0, h0));
    r.y = fmaxf(0.f, fmaf(s1 >= 0.f ? mx.y : mn.y, s1, h1));
    r.z = fmaxf(0.f, fmaf(s2 >= 0.f ? mx.z : mn.z, s2, h2));
    r.w = fmaxf(0.f, fmaf(s3 >= 0.f ? mx.w : mn.w, s3, h3));
    *(float4*)(out + NEWPOS_ELEMS + (size_t)row*CO + c) = r;
}

// ---------------- launch ----------------
extern "C" void kernel_launch(void* const* d_in, const int* in_sizes, int n_in,
                              void* d_out, int out_size)
{
    const float* pos    = (const float*)d_in[0];
    const float* points = (const float*)d_in[1];
    const int*   idx    = (const int*)  d_in[2];
    const float* W1     = (const float*)d_in[3];
    const float* b1     = (const float*)d_in[4];
    const float* g1     = (const float*)d_in[5];
    const float* beta1  = (const float*)d_in[6];
    const float* W2     = (const float*)d_in[7];
    const float* b2     = (const float*)d_in[8];
    const float* g2     = (const float*)d_in[9];
    const float* beta2  = (const float*)d_in[10];
    float* out = (float*)d_out;

    float *pP;
    cudaGetSymbolAddress((void**)&pP, g_P);

    cudaFuncSetAttribute(gemm2_mma_kernel,
                         cudaFuncAttributeMaxDynamicSharedMemorySize, SMEM_G2);

    // launch 0: kNN (+ zero stats) — 256 thr, 128 blocks = single wave
    knn_kernel<<<QTOT/256, 256>>>(pos, idx, out);
    // launch 1: P = points @ W1p^T (+ W2 bf16 split)
    gemm_p_kernel<<<dim3((BB*NN)/128, CO/128), 256>>>(points, CC, W1, CI1, 3, pP, CC, W2);
    // launch 2: h1 assembly + BN1 stats
    assemble_h1_kernel<<<ROWS/64, 256>>>(pos, idx, W1, b1);
    // launch 3: GEMM2 (tensor cores) + BN2 stats + pooled epilogue   <- ncu target
    gemm2_mma_kernel<<<148, 512, SMEM_G2>>>(b2, g1, beta1);
    // launch 4: BN2 finalize + output
    final_out_kernel<<<(QTOT*64)/256, 256>>>(out, g2, beta2);
}